// round 13
// baseline (speedup 1.0000x reference)
#include <cuda_runtime.h>
#include <cuda_bf16.h>
#include <cstdint>
#include <cstddef>

// ---------------- problem constants ----------------
#define SS      4096
#define EMB     2048
#define PROJD   10304
#define PROJPAD 10368
#define INTERD  4096
#define CONVD   6144
#define NH      64
#define HP      64
#define SN      128
#define NG      8
#define CSZ     256
#define NCH     16
#define DTOFF   10240
#define BCW     2048

// ---------------- scratch ----------------
__device__ float g_proj[(size_t)SS * PROJD];
__device__ float g_hconv[(size_t)SS * CONVD];
__device__ float g_dt2[SS * NH];
__device__ float g_acum[NH * SS];
__device__ float g_y[(size_t)SS * INTERD];
__device__ __nv_bfloat16 g_bch[(size_t)SS * BCW];
__device__ __nv_bfloat16 g_bcl[(size_t)SS * BCW];
// dedup split operands: [hi | lo], 2K wide
__device__ __nv_bfloat16 g_Apack[(size_t)SS * 2 * INTERD];
__device__ __nv_bfloat16 g_B1[(size_t)PROJPAD * 2 * EMB];
__device__ __nv_bfloat16 g_B2[(size_t)EMB * 2 * INTERD];

// ================= helpers =================
__device__ __forceinline__ uint32_t smem_u32(const void* p) {
    uint32_t a;
    asm("{ .reg .u64 t; cvta.to.shared.u64 t, %1; cvt.u32.u64 %0, t; }" : "=r"(a) : "l"(p));
    return a;
}
__device__ __forceinline__ void cp_async16(uint32_t saddr, const void* g) {
    asm volatile("cp.async.cg.shared.global [%0], [%1], 16;" :: "r"(saddr), "l"(g) : "memory");
}
#define CP_COMMIT() asm volatile("cp.async.commit_group;" ::: "memory")

__device__ __forceinline__ void ldsm_x4(uint32_t addr, uint32_t& r0, uint32_t& r1,
                                        uint32_t& r2, uint32_t& r3) {
    asm volatile("ldmatrix.sync.aligned.m8n8.x4.shared.b16 {%0,%1,%2,%3}, [%4];"
                 : "=r"(r0), "=r"(r1), "=r"(r2), "=r"(r3) : "r"(addr));
}
__device__ __forceinline__ void mma_bf16(float* d, const uint32_t* a, uint32_t b0, uint32_t b1) {
    asm volatile(
        "mma.sync.aligned.m16n8k16.row.col.f32.bf16.bf16.f32 "
        "{%0,%1,%2,%3}, {%4,%5,%6,%7}, {%8,%9}, {%0,%1,%2,%3};"
        : "+f"(d[0]), "+f"(d[1]), "+f"(d[2]), "+f"(d[3])
        : "r"(a[0]), "r"(a[1]), "r"(a[2]), "r"(a[3]), "r"(b0), "r"(b1));
}
__device__ __forceinline__ uint32_t pack_bf2(float x, float y) {
    __nv_bfloat16 a = __float2bfloat16(x);
    __nv_bfloat16 b = __float2bfloat16(y);
    return (uint32_t)__bfloat16_as_ushort(a) | ((uint32_t)__bfloat16_as_ushort(b) << 16);
}

// ================= split-pack: dst row = [hi | lo], stride 2K =================
__global__ void pack_split(const float* __restrict__ src, __nv_bfloat16* __restrict__ dst,
                           int srcRows, int rowStart, int rowEnd, int K) {
    const int K8 = K >> 3;
    const size_t total = (size_t)(rowEnd - rowStart) * K8;
    for (size_t v = (size_t)blockIdx.x * 256 + threadIdx.x; v < total;
         v += (size_t)gridDim.x * 256) {
        const int r = rowStart + (int)(v / K8);
        const int k = (int)(v % K8) << 3;
        float x[8];
        if (r < srcRows) {
            const float4 f0 = *(const float4*)(src + (size_t)r * K + k);
            const float4 f1 = *(const float4*)(src + (size_t)r * K + k + 4);
            x[0] = f0.x; x[1] = f0.y; x[2] = f0.z; x[3] = f0.w;
            x[4] = f1.x; x[5] = f1.y; x[6] = f1.z; x[7] = f1.w;
        } else {
#pragma unroll
            for (int i = 0; i < 8; i++) x[i] = 0.f;
        }
        union { __nv_bfloat16 h[8]; uint4 u; } uh, ul;
#pragma unroll
        for (int i = 0; i < 8; i++) {
            uh.h[i] = __float2bfloat16(x[i]);
            ul.h[i] = __float2bfloat16(x[i] - __bfloat162float(uh.h[i]));
        }
        const size_t ro = (size_t)r * 2 * K + k;
        *(uint4*)(dst + ro) = uh.u;
        *(uint4*)(dst + ro + K) = ul.u;
    }
}

// ================= HMMA GEMM, CTA 256x128, warp tile 64x64, 4-stage =================
// Virtual K3=3K over [hi|lo] dedup storage.
// A term order: hi, lo, hi -> kA = k0 < 2K ? k0 : k0 - 2K
// B term order: hi, hi, lo -> kB = k0 <  K ? k0 : k0 -  K
#define GSTAGES 4
#define GSTAGE_BYTES 49152          // A 32KB (256x128B) + B 16KB (128x128B)
#define GEMM_DYN_SMEM (GSTAGES * GSTAGE_BYTES)

__device__ __forceinline__ void gemm_load_stage(
    const __nv_bfloat16* __restrict__ A, const __nv_bfloat16* __restrict__ B,
    int Kb, int m0, int n0, int tid, uint32_t sb, int stage, int kk) {
    const uint32_t abase = sb + stage * GSTAGE_BYTES;
    const uint32_t bbase = abase + 32768;
    const int k0 = kk * 64;
    const int kA = (k0 < 2 * Kb) ? k0 : k0 - 2 * Kb;
    const int kB = (k0 < Kb) ? k0 : k0 - Kb;
    const int rs = 2 * Kb;
#pragma unroll
    for (int it = 0; it < 8; it++) {
        const int idx = it * 256 + tid;      // 0..2047 -> 256 rows x 8 chunks
        const int row = idx >> 3;
        const int ch = idx & 7;
        const int csw = ch ^ (row & 7);
        cp_async16(abase + row * 128 + csw * 16,
                   A + (size_t)(m0 + row) * rs + kA + ch * 8);
    }
#pragma unroll
    for (int it = 0; it < 4; it++) {
        const int idx = it * 256 + tid;      // 0..1023 -> 128 rows x 8 chunks
        const int row = idx >> 3;
        const int ch = idx & 7;
        const int csw = ch ^ (row & 7);
        cp_async16(bbase + row * 128 + csw * 16,
                   B + (size_t)(n0 + row) * rs + kB + ch * 8);
    }
}

__global__ __launch_bounds__(256, 1)
void tgemm(const __nv_bfloat16* __restrict__ A, const __nv_bfloat16* __restrict__ B,
           float* __restrict__ C, int Kb, int Nvalid, int Nstride) {
    extern __shared__ char dynsm[];
    const uint32_t sb = smem_u32(dynsm);
    const int tid = threadIdx.x;
    const int lane = tid & 31;
    const int wid = tid >> 5;
    const int wm = wid & 3;          // 4 warps along M (64 rows each)
    const int wn = wid >> 2;         // 2 warps along N (64 cols each)
    const int m0 = blockIdx.x * 256; // M fastest-varying -> A slab L2-resident
    const int n0 = blockIdx.y * 128;
    const int nK = (3 * Kb) >> 6;

    float acc[4][8][4];
#pragma unroll
    for (int i = 0; i < 4; i++)
#pragma unroll
        for (int j = 0; j < 8; j++)
#pragma unroll
            for (int q = 0; q < 4; q++) acc[i][j][q] = 0.f;

    gemm_load_stage(A, B, Kb, m0, n0, tid, sb, 0, 0); CP_COMMIT();
    gemm_load_stage(A, B, Kb, m0, n0, tid, sb, 1, 1); CP_COMMIT();
    gemm_load_stage(A, B, Kb, m0, n0, tid, sb, 2, 2); CP_COMMIT();

    const int a_row = wm * 64 + (lane & 15);        // + mi*16, mi in 0..3
    const int a_chg = lane >> 4;
    const int b_g = lane >> 3;
    const int b_row = wn * 64 + ((b_g >> 1) << 3) + (lane & 7);  // + nb*16
    const int b_chg = b_g & 1;

    int buf = 0, nbuf = 3;
    for (int i = 0; i < nK; i++) {
        asm volatile("cp.async.wait_group 2;" ::: "memory");
        __syncthreads();
        if (i + 3 < nK) gemm_load_stage(A, B, Kb, m0, n0, tid, sb, nbuf, i + 3);
        CP_COMMIT();

        const uint32_t abase = sb + buf * GSTAGE_BYTES;
        const uint32_t bbase = abase + 32768;
#pragma unroll
        for (int kk = 0; kk < 4; kk++) {
            uint32_t af[4][4];
#pragma unroll
            for (int mi = 0; mi < 4; mi++) {
                const int row = a_row + mi * 16;
                const int ch = kk * 2 + a_chg;
                const int csw = ch ^ (row & 7);
                ldsm_x4(abase + row * 128 + csw * 16,
                        af[mi][0], af[mi][1], af[mi][2], af[mi][3]);
            }
            uint32_t bf[4][4];
#pragma unroll
            for (int nb = 0; nb < 4; nb++) {
                const int row = b_row + nb * 16;
                const int ch = kk * 2 + b_chg;
                const int csw = ch ^ (row & 7);
                ldsm_x4(bbase + row * 128 + csw * 16,
                        bf[nb][0], bf[nb][1], bf[nb][2], bf[nb][3]);
            }
#pragma unroll
            for (int mi = 0; mi < 4; mi++)
#pragma unroll
                for (int nb = 0; nb < 4; nb++) {
                    mma_bf16(acc[mi][nb * 2 + 0], af[mi], bf[nb][0], bf[nb][1]);
                    mma_bf16(acc[mi][nb * 2 + 1], af[mi], bf[nb][2], bf[nb][3]);
                }
        }
        buf = (buf + 1 == GSTAGES) ? 0 : buf + 1;
        nbuf = (nbuf + 1 == GSTAGES) ? 0 : nbuf + 1;
    }

    const int erow = (lane >> 2);
    const int ecol = (lane & 3) << 1;
#pragma unroll
    for (int mi = 0; mi < 4; mi++) {
        const int r = m0 + wm * 64 + mi * 16 + erow;
#pragma unroll
        for (int f = 0; f < 8; f++) {
            const int c = n0 + wn * 64 + (f >> 1) * 16 + (f & 1) * 8 + ecol;
            if (c < Nvalid) {
                *(float2*)(C + (size_t)r * Nstride + c) =
                    make_float2(acc[mi][f][0], acc[mi][f][1]);
                *(float2*)(C + (size_t)(r + 8) * Nstride + c) =
                    make_float2(acc[mi][f][2], acc[mi][f][3]);
            }
        }
    }
}

// -------- depthwise causal conv (K=4) + bias + silu, 8 t/thread --------
__global__ void conv_silu_kernel(const float* __restrict__ cw, const float* __restrict__ cb) {
    const int c = blockIdx.x * 256 + threadIdx.x;
    const int tb = blockIdx.y * 8;
    const float w0 = cw[c * 4 + 0], w1 = cw[c * 4 + 1],
                w2 = cw[c * 4 + 2], w3 = cw[c * 4 + 3];
    const float bias = cb[c];
    float v[11];
#pragma unroll
    for (int k = 0; k < 11; k++) {
        const int tt = tb - 3 + k;
        v[k] = (tt >= 0) ? g_proj[(size_t)tt * PROJD + INTERD + c] : 0.f;
    }
    if (c < INTERD) {
#pragma unroll
        for (int j = 0; j < 8; j++) {
            const float a = bias + v[j] * w0 + v[j + 1] * w1 + v[j + 2] * w2 + v[j + 3] * w3;
            g_hconv[(size_t)(tb + j) * CONVD + c] = a / (1.f + __expf(-a));
        }
    } else {
        const int cc = c - INTERD;
#pragma unroll
        for (int j = 0; j < 8; j++) {
            const float a = bias + v[j] * w0 + v[j + 1] * w1 + v[j + 2] * w2 + v[j + 3] * w3;
            const float y = a / (1.f + __expf(-a));
            const __nv_bfloat16 hb = __float2bfloat16(y);
            g_bch[(size_t)(tb + j) * BCW + cc] = hb;
            g_bcl[(size_t)(tb + j) * BCW + cc] =
                __float2bfloat16(y - __bfloat162float(hb));
        }
    }
}

// ---------------- fused softplus(dt)+cumsum per (chunk, head) ----------------
__global__ void dtacum_kernel(const float* __restrict__ dt_bias,
                              const float* __restrict__ A_log) {
    const int chunk = blockIdx.x;
    const int h = blockIdx.y;
    const int tid = threadIdx.x;
    const float Ah = -expf(A_log[h]);
    const float bias = dt_bias[h];
    __shared__ float s[CSZ];
    const int t = chunk * CSZ + tid;
    const float x = g_proj[(size_t)t * PROJD + DTOFF + h] + bias;
    const float dt2 = (x > 20.f) ? x : log1pf(expf(x));
    g_dt2[t * NH + h] = dt2;
    s[tid] = Ah * dt2;
    for (int off = 1; off < CSZ; off <<= 1) {
        __syncthreads();
        const float v = (tid >= off) ? s[tid - off] : 0.f;
        __syncthreads();
        s[tid] += v;
    }
    g_acum[h * SS + t] = s[tid];
}

// ================= SSD via HMMA (split-bf16 3-term), R10 structure =================
#define S_CHI 0
#define S_CLO 65536
#define S_GWH 131072
#define S_BHI 131072
#define S_BLO 147456
#define S_GWL 163840
#define S_XHI 196608
#define S_XLO 204800
#define S_ACS 212992
#define SSD_DYN_SMEM (S_ACS + 1024)

__global__ __launch_bounds__(256, 1)
void ssd_hmma(const float* __restrict__ Dp) {
    extern __shared__ char sm[];
    const uint32_t sb = smem_u32(sm);
    float* acs = (float*)(sm + S_ACS);
    const int tid = threadIdx.x;
    const int lane = tid & 31;
    const int w = tid >> 5;
    const int chunk = blockIdx.x;
    const int h = blockIdx.y;
    const int t0 = chunk * CSZ;
    const int grp = h & 7;
    const int Bcol = grp * SN;
    const int Ccol = NG * SN + grp * SN;
    const int i0 = w * 32;

#pragma unroll 4
    for (int it = 0; it < 16; it++) {
        const int u = it * 256 + tid;
        const int i = u >> 4;
        const int nb = u & 15;
        const uint32_t dsw = i * 256 + ((nb ^ (i & 7)) << 4);
        const size_t gsrc = (size_t)(t0 + i) * BCW + Ccol + nb * 8;
        cp_async16(sb + S_CHI + dsw, g_bch + gsrc);
        cp_async16(sb + S_CLO + dsw, g_bcl + gsrc);
    }
    CP_COMMIT();

    acs[tid] = g_acum[h * SS + t0 + tid];

    float yacc[2][8][4];
#pragma unroll
    for (int mi = 0; mi < 2; mi++)
#pragma unroll
        for (int nb = 0; nb < 8; nb++)
#pragma unroll
            for (int q = 0; q < 4; q++) yacc[mi][nb][q] = 0.f;

    const int ro = lane >> 2;
    const int co = (lane & 3) * 2;

    for (int jt = 0; jt < 4; jt++) {
        const int jb = jt * 64;
#pragma unroll
        for (int it = 0; it < 4; it++) {
            const int u = it * 256 + tid;
            const int j = u >> 4;
            const int nb = u & 15;
            const uint32_t dsw = j * 256 + ((nb ^ (j & 7)) << 4);
            const size_t gsrc = (size_t)(t0 + jb + j) * BCW + Bcol + nb * 8;
            cp_async16(sb + S_BHI + dsw, g_bch + gsrc);
            cp_async16(sb + S_BLO + dsw, g_bcl + gsrc);
        }
        CP_COMMIT();
#pragma unroll
        for (int it = 0; it < 4; it++) {
            const int u = it * 256 + tid;
            const int j = u >> 4;
            const int pb = (u & 15) * 4;
            const int tj = t0 + jb + j;
            float4 v = *(const float4*)(g_hconv + (size_t)tj * CONVD + h * HP + pb);
            const float sc = g_dt2[tj * NH + h];
            const float xv[4] = {v.x * sc, v.y * sc, v.z * sc, v.w * sc};
            const int wo = (j * 2) & 15;
            const int chn = j >> 3;
#pragma unroll
            for (int q = 0; q < 4; q++) {
                const int p = pb + q;
                const __nv_bfloat16 hb = __float2bfloat16(xv[q]);
                const __nv_bfloat16 lb = __float2bfloat16(xv[q] - __bfloat162float(hb));
                const uint32_t ad = p * 128 + ((chn ^ (p & 7)) << 4) + wo;
                *(__nv_bfloat16*)(sm + S_XHI + ad) = hb;
                *(__nv_bfloat16*)(sm + S_XLO + ad) = lb;
            }
        }
        asm volatile("cp.async.wait_group 0;" ::: "memory");
        __syncthreads();

        const float alast = acs[CSZ - 1];

        float gacc[2][8][4];
#pragma unroll
        for (int mi = 0; mi < 2; mi++)
#pragma unroll
            for (int nb = 0; nb < 8; nb++)
#pragma unroll
                for (int q = 0; q < 4; q++) gacc[mi][nb][q] = 0.f;

        for (int term = 0; term < 3; term++) {
            const uint32_t Ab = sb + ((term == 1) ? S_CLO : S_CHI);
            const uint32_t Bb = sb + ((term == 2) ? S_BLO : S_BHI);
#pragma unroll
            for (int ks = 0; ks < 8; ks++) {
                uint32_t af[2][4];
#pragma unroll
                for (int mi = 0; mi < 2; mi++) {
                    const int row = i0 + mi * 16 + (lane & 15);
                    const int ch = 2 * ks + (lane >> 4);
                    const int csw = ch ^ (row & 7);
                    ldsm_x4(Ab + row * 256 + csw * 16,
                            af[mi][0], af[mi][1], af[mi][2], af[mi][3]);
                }
#pragma unroll
                for (int q = 0; q < 4; q++) {
                    const int bg = lane >> 3;
                    const int brow = q * 16 + ((bg >> 1) << 3) + (lane & 7);
                    const int bch = 2 * ks + (bg & 1);
                    const int bcsw = bch ^ (brow & 7);
                    uint32_t b0, b1, b2, b3;
                    ldsm_x4(Bb + brow * 256 + bcsw * 16, b0, b1, b2, b3);
                    mma_bf16(gacc[0][q * 2 + 0], af[0], b0, b1);
                    mma_bf16(gacc[0][q * 2 + 1], af[0], b2, b3);
                    mma_bf16(gacc[1][q * 2 + 0], af[1], b0, b1);
                    mma_bf16(gacc[1][q * 2 + 1], af[1], b2, b3);
                }
            }
        }

#pragma unroll
        for (int mi = 0; mi < 2; mi++) {
            const int r1 = i0 + mi * 16 + ro;
            const int r2 = r1 + 8;
            const float a1 = acs[r1];
            const float a2 = acs[r2];
#pragma unroll
            for (int nb = 0; nb < 8; nb++) {
                const int cb = (nb >> 1) * 16 + (nb & 1) * 8 + co;
                const int jg = jb + cb;
                const float aj0 = acs[jg];
                const float aj1 = acs[jg + 1];
                float wv;
                wv = __expf(a1 - aj0 + alast) + ((jg     <= r1) ? __expf(a1 - aj0) : 0.f);
                gacc[mi][nb][0] *= wv;
                wv = __expf(a1 - aj1 + alast) + ((jg + 1 <= r1) ? __expf(a1 - aj1) : 0.f);
                gacc[mi][nb][1] *= wv;
                wv = __expf(a2 - aj0 + alast) + ((jg     <= r2) ? __expf(a2 - aj0) : 0.f);
                gacc[mi][nb][2] *= wv;
                wv = __expf(a2 - aj1 + alast) + ((jg + 1 <= r2) ? __expf(a2 - aj1) : 0.f);
                gacc[mi][nb][3] *= wv;
            }
        }
        __syncthreads();

#pragma unroll
        for (int mi = 0; mi < 2; mi++) {
            const int r1 = i0 + mi * 16 + ro;
            const int r2 = r1 + 8;
#pragma unroll
            for (int nb = 0; nb < 8; nb++) {
                const int c = (nb >> 1) * 16 + (nb & 1) * 8 + co;
                const int chn = c >> 3;
                const int wo = (c * 2) & 15;
                const uint32_t ad1 = r1 * 128 + ((chn ^ (r1 & 7)) << 4) + wo;
                const uint32_t ad2 = r2 * 128 + ((chn ^ (r2 & 7)) << 4) + wo;
                *(uint32_t*)(sm + S_GWH + ad1) = pack_bf2(gacc[mi][nb][0], gacc[mi][nb][1]);
                *(uint32_t*)(sm + S_GWL + ad1) = pack_bf2(
                    gacc[mi][nb][0] - __bfloat162float(__float2bfloat16(gacc[mi][nb][0])),
                    gacc[mi][nb][1] - __bfloat162float(__float2bfloat16(gacc[mi][nb][1])));
                *(uint32_t*)(sm + S_GWH + ad2) = pack_bf2(gacc[mi][nb][2], gacc[mi][nb][3]);
                *(uint32_t*)(sm + S_GWL + ad2) = pack_bf2(
                    gacc[mi][nb][2] - __bfloat162float(__float2bfloat16(gacc[mi][nb][2])),
                    gacc[mi][nb][3] - __bfloat162float(__float2bfloat16(gacc[mi][nb][3])));
            }
        }
        __syncthreads();

        for (int term = 0; term < 3; term++) {
            const uint32_t Ab = sb + ((term == 1) ? S_GWL : S_GWH);
            const uint32_t Bb = sb + ((term == 2) ? S_XLO : S_XHI);
#pragma unroll
            for (int ks = 0; ks < 4; ks++) {
                uint32_t af[2][4];
#pragma unroll
                for (int mi = 0; mi < 2; mi++) {
                    const int row = i0 + mi * 16 + (lane & 15);
                    const int ch = 2 * ks + (lane >> 4);
                    const int csw = ch ^ (row & 7);
                    ldsm_x4(Ab + row * 128 + csw * 16,
                            af[mi][0], af[mi][1], af[mi][2], af[mi][3]);
                }
#pragma unroll
                for (int q = 0; q < 4; q++) {
                    const int bg = lane >> 3;
                    const int brow = q * 16 + ((bg >> 1) << 3) + (lane & 7);
                    const int bch = 2 * ks + (bg & 1);
                    const int bcsw = bch ^ (brow & 7);
                    uint32_t b0, b1, b2, b3;
                    ldsm_x4(Bb + brow * 128 + bcsw * 16, b0, b1, b2, b3);
                    mma_bf16(yacc[0][q * 2 + 0], af[0], b0, b1);
                    mma_bf16(yacc[0][q * 2 + 1], af[0], b2, b3);
                    mma_bf16(yacc[1][q * 2 + 0], af[1], b0, b1);
                    mma_bf16(yacc[1][q * 2 + 1], af[1], b2, b3);
                }
            }
        }
        __syncthreads();
    }

    const float Dh = Dp[h];
#pragma unroll
    for (int mi = 0; mi < 2; mi++) {
        const int r1 = t0 + i0 + mi * 16 + ro;
        const int r2 = r1 + 8;
#pragma unroll
        for (int nb = 0; nb < 8; nb++) {
            const int p = (nb >> 1) * 16 + (nb & 1) * 8 + co;
            const float2 h1 = *(const float2*)(g_hconv + (size_t)r1 * CONVD + h * HP + p);
            const float2 h2 = *(const float2*)(g_hconv + (size_t)r2 * CONVD + h * HP + p);
            *(float2*)(g_y + (size_t)r1 * INTERD + h * HP + p) =
                make_float2(yacc[mi][nb][0] + Dh * h1.x, yacc[mi][nb][1] + Dh * h1.y);
            *(float2*)(g_y + (size_t)r2 * INTERD + h * HP + p) =
                make_float2(yacc[mi][nb][2] + Dh * h2.x, yacc[mi][nb][3] + Dh * h2.y);
        }
    }
}

// ---------------- gate silu + RMSNorm + split-bf16 A-pack ([hi|lo]) ----------------
__global__ void norm_pack_kernel(const float* __restrict__ norm_w) {
    const int t = blockIdx.x;
    const int tid = threadIdx.x;
    __shared__ float red[256];
    __shared__ float yg_s[INTERD];
    float local = 0.f;
    for (int c = tid; c < INTERD; c += 256) {
        const float g = g_proj[(size_t)t * PROJD + c];
        const float yv = g_y[(size_t)t * INTERD + c];
        const float yg = yv * (g / (1.f + __expf(-g)));
        yg_s[c] = yg;
        local += yg * yg;
    }
    red[tid] = local;
    __syncthreads();
    for (int s = 128; s > 0; s >>= 1) {
        if (tid < s) red[tid] += red[tid + s];
        __syncthreads();
    }
    const float rstd = rsqrtf(red[0] / (float)INTERD + 1e-6f);
    __nv_bfloat16* dst = g_Apack + (size_t)t * 2 * INTERD;
    for (int c = tid * 4; c < INTERD; c += 1024) {
        union { __nv_bfloat16 h[4]; uint2 u; } uh, ul;
#pragma unroll
        for (int i = 0; i < 4; i++) {
            const float v = norm_w[c + i] * yg_s[c + i] * rstd;
            uh.h[i] = __float2bfloat16(v);
            ul.h[i] = __float2bfloat16(v - __bfloat162float(uh.h[i]));
        }
        *(uint2*)(dst + c) = uh.u;
        *(uint2*)(dst + INTERD + c) = ul.u;
    }
}

// ---------------- launch ----------------
extern "C" void kernel_launch(void* const* d_in, const int* in_sizes, int n_in,
                              void* d_out, int out_size) {
    (void)in_sizes; (void)n_in; (void)out_size;
    const float* x       = (const float*)d_in[0];
    const float* w_in    = (const float*)d_in[1];
    const float* conv_w  = (const float*)d_in[2];
    const float* conv_b  = (const float*)d_in[3];
    const float* dt_bias = (const float*)d_in[4];
    const float* A_log   = (const float*)d_in[5];
    const float* Dv      = (const float*)d_in[6];
    const float* norm_w  = (const float*)d_in[7];
    const float* w_out   = (const float*)d_in[8];
    float* out = (float*)d_out;

    float* p_proj = nullptr;
    __nv_bfloat16* p_Apack = nullptr;
    __nv_bfloat16* p_B1 = nullptr;
    __nv_bfloat16* p_B2 = nullptr;
    cudaGetSymbolAddress((void**)&p_proj, g_proj);
    cudaGetSymbolAddress((void**)&p_Apack, g_Apack);
    cudaGetSymbolAddress((void**)&p_B1, g_B1);
    cudaGetSymbolAddress((void**)&p_B2, g_B2);

    cudaFuncSetAttribute(tgemm, cudaFuncAttributeMaxDynamicSharedMemorySize, GEMM_DYN_SMEM);
    cudaFuncSetAttribute(ssd_hmma, cudaFuncAttributeMaxDynamicSharedMemorySize, SSD_DYN_SMEM);

    // --- GEMM1 packs (split so tgemm is the 4th launch for ncu) ---
    pack_split<<<2048, 256>>>(x, p_Apack, SS, 0, SS, EMB);
    pack_split<<<2048, 256>>>(w_in, p_B1, PROJD, 0, PROJPAD / 2, EMB);
    pack_split<<<2048, 256>>>(w_in, p_B1, PROJD, PROJPAD / 2, PROJPAD, EMB);
    // --- GEMM1: proj = X @ W_in^T ---
    tgemm<<<dim3(SS / 256, PROJPAD / 128), 256, GEMM_DYN_SMEM>>>(
        p_Apack, p_B1, p_proj, EMB, PROJD, PROJD);

    // --- elementwise / scan stages ---
    conv_silu_kernel<<<dim3(CONVD / 256, SS / 8), 256>>>(conv_w, conv_b);
    dtacum_kernel<<<dim3(NCH, NH), CSZ>>>(dt_bias, A_log);
    ssd_hmma<<<dim3(NCH, NH), 256, SSD_DYN_SMEM>>>(Dv);
    norm_pack_kernel<<<SS, 256>>>(norm_w);

    // --- GEMM2: out = normed @ W_out^T ---
    pack_split<<<2048, 256>>>(w_out, p_B2, EMB, 0, EMB, INTERD);
    tgemm<<<dim3(SS / 256, EMB / 128), 256, GEMM_DYN_SMEM>>>(
        p_Apack, p_B2, out, INTERD, EMB, EMB);
}

// round 14
// speedup vs baseline: 1.0421x; 1.0421x over previous
#include <cuda_runtime.h>
#include <cuda_bf16.h>
#include <cstdint>
#include <cstddef>

// ---------------- problem constants ----------------
#define SS      4096
#define EMB     2048
#define PROJD   10304
#define PROJPAD 10368
#define INTERD  4096
#define CONVD   6144
#define NH      64
#define HP      64
#define SN      128
#define NG      8
#define CSZ     256
#define NCH     16
#define DTOFF   10240
#define BCW     2048

// ---------------- scratch ----------------
__device__ float g_proj[(size_t)SS * PROJD];
__device__ float g_hconv[(size_t)SS * CONVD];
__device__ float g_dt2[SS * NH];
__device__ float g_acum[NH * SS];
__device__ float g_y[(size_t)SS * INTERD];
__device__ __nv_bfloat16 g_bch[(size_t)SS * BCW];
__device__ __nv_bfloat16 g_bcl[(size_t)SS * BCW];
__device__ __nv_bfloat16 g_Apack[(size_t)SS * 3 * INTERD];
__device__ __nv_bfloat16 g_B1[(size_t)PROJPAD * 3 * EMB];
__device__ __nv_bfloat16 g_B2[(size_t)EMB * 3 * INTERD];

// ================= helpers =================
__device__ __forceinline__ uint32_t smem_u32(const void* p) {
    uint32_t a;
    asm("{ .reg .u64 t; cvta.to.shared.u64 t, %1; cvt.u32.u64 %0, t; }" : "=r"(a) : "l"(p));
    return a;
}
__device__ __forceinline__ void cp_async16(uint32_t saddr, const void* g) {
    asm volatile("cp.async.cg.shared.global [%0], [%1], 16;" :: "r"(saddr), "l"(g) : "memory");
}
#define CP_COMMIT() asm volatile("cp.async.commit_group;" ::: "memory")

__device__ __forceinline__ void ldsm_x4(uint32_t addr, uint32_t& r0, uint32_t& r1,
                                        uint32_t& r2, uint32_t& r3) {
    asm volatile("ldmatrix.sync.aligned.m8n8.x4.shared.b16 {%0,%1,%2,%3}, [%4];"
                 : "=r"(r0), "=r"(r1), "=r"(r2), "=r"(r3) : "r"(addr));
}
__device__ __forceinline__ void mma_bf16(float* d, const uint32_t* a, uint32_t b0, uint32_t b1) {
    asm volatile(
        "mma.sync.aligned.m16n8k16.row.col.f32.bf16.bf16.f32 "
        "{%0,%1,%2,%3}, {%4,%5,%6,%7}, {%8,%9}, {%0,%1,%2,%3};"
        : "+f"(d[0]), "+f"(d[1]), "+f"(d[2]), "+f"(d[3])
        : "r"(a[0]), "r"(a[1]), "r"(a[2]), "r"(a[3]), "r"(b0), "r"(b1));
}
__device__ __forceinline__ uint32_t pack_bf2(float x, float y) {
    __nv_bfloat16 a = __float2bfloat16(x);
    __nv_bfloat16 b = __float2bfloat16(y);
    return (uint32_t)__bfloat16_as_ushort(a) | ((uint32_t)__bfloat16_as_ushort(b) << 16);
}

// ================= split-pack (R10: 3K storage, mode-based) =================
// mode 0 (A): [hi | lo | hi]; mode 1 (B): [hi | hi | lo]
__global__ void pack_split(const float* __restrict__ src, __nv_bfloat16* __restrict__ dst,
                           int srcRows, int rowStart, int rowEnd, int K, int mode) {
    const int K8 = K >> 3;
    const size_t total = (size_t)(rowEnd - rowStart) * K8;
    for (size_t v = (size_t)blockIdx.x * 256 + threadIdx.x; v < total;
         v += (size_t)gridDim.x * 256) {
        const int r = rowStart + (int)(v / K8);
        const int k = (int)(v % K8) << 3;
        float x[8];
        if (r < srcRows) {
            const float4 f0 = *(const float4*)(src + (size_t)r * K + k);
            const float4 f1 = *(const float4*)(src + (size_t)r * K + k + 4);
            x[0] = f0.x; x[1] = f0.y; x[2] = f0.z; x[3] = f0.w;
            x[4] = f1.x; x[5] = f1.y; x[6] = f1.z; x[7] = f1.w;
        } else {
#pragma unroll
            for (int i = 0; i < 8; i++) x[i] = 0.f;
        }
        union { __nv_bfloat16 h[8]; uint4 u; } uh, ul;
#pragma unroll
        for (int i = 0; i < 8; i++) {
            uh.h[i] = __float2bfloat16(x[i]);
            ul.h[i] = __float2bfloat16(x[i] - __bfloat162float(uh.h[i]));
        }
        const size_t ro = (size_t)r * 3 * K + k;
        *(uint4*)(dst + ro) = uh.u;
        if (mode == 0) {
            *(uint4*)(dst + ro + K) = ul.u;
            *(uint4*)(dst + ro + 2 * K) = uh.u;
        } else {
            *(uint4*)(dst + ro + K) = uh.u;
            *(uint4*)(dst + ro + 2 * K) = ul.u;
        }
    }
}

// ================= HMMA GEMM (R10 exact): CTA 128x128, BK=64, 3-stage, 2 CTA/SM ======
#define GSTAGES 3
#define GSTAGE_BYTES 32768
#define GEMM_DYN_SMEM (GSTAGES * GSTAGE_BYTES)

__device__ __forceinline__ void gemm_load_stage(
    const __nv_bfloat16* __restrict__ A, const __nv_bfloat16* __restrict__ B,
    int K3, int m0, int n0, int tid, uint32_t sb, int stage, int kk) {
    const uint32_t abase = sb + stage * GSTAGE_BYTES;
    const uint32_t bbase = abase + 16384;
    const int k0 = kk * 64;
#pragma unroll
    for (int it = 0; it < 4; it++) {
        const int idx = it * 256 + tid;
        const int row = idx >> 3;
        const int ch = idx & 7;
        const int csw = ch ^ (row & 7);
        cp_async16(abase + row * 128 + csw * 16,
                   A + (size_t)(m0 + row) * K3 + k0 + ch * 8);
    }
#pragma unroll
    for (int it = 0; it < 4; it++) {
        const int idx = it * 256 + tid;
        const int row = idx >> 3;
        const int ch = idx & 7;
        const int csw = ch ^ (row & 7);
        cp_async16(bbase + row * 128 + csw * 16,
                   B + (size_t)(n0 + row) * K3 + k0 + ch * 8);
    }
}

__global__ __launch_bounds__(256, 2)
void tgemm(const __nv_bfloat16* __restrict__ A, const __nv_bfloat16* __restrict__ B,
           float* __restrict__ C, int K3, int Nvalid, int Nstride) {
    extern __shared__ char dynsm[];
    const uint32_t sb = smem_u32(dynsm);
    const int tid = threadIdx.x;
    const int lane = tid & 31;
    const int wid = tid >> 5;
    const int wm = wid & 3;
    const int wn = wid >> 2;

    const int gridM = gridDim.x;
    const int gridN = gridDim.y;
    const int bid = blockIdx.y * gridM + blockIdx.x;
    const int GM = 16;
    const int group = bid / (GM * gridN);
    const int rem = bid - group * (GM * gridN);
    const int m0 = (group * GM + (rem % GM)) * 128;
    const int n0 = (rem / GM) * 128;
    const int nK = K3 >> 6;

    float acc[2][8][4];
#pragma unroll
    for (int i = 0; i < 2; i++)
#pragma unroll
        for (int j = 0; j < 8; j++)
#pragma unroll
            for (int q = 0; q < 4; q++) acc[i][j][q] = 0.f;

    gemm_load_stage(A, B, K3, m0, n0, tid, sb, 0, 0); CP_COMMIT();
    gemm_load_stage(A, B, K3, m0, n0, tid, sb, 1, 1); CP_COMMIT();

    const int a_row = wm * 32 + (lane & 15);
    const int a_chg = lane >> 4;
    const int b_g = lane >> 3;
    const int b_row = wn * 64 + ((b_g >> 1) << 3) + (lane & 7);
    const int b_chg = b_g & 1;

    int buf = 0, nbuf = 2;
    for (int i = 0; i < nK; i++) {
        asm volatile("cp.async.wait_group 1;" ::: "memory");
        __syncthreads();
        if (i + 2 < nK) gemm_load_stage(A, B, K3, m0, n0, tid, sb, nbuf, i + 2);
        CP_COMMIT();

        const uint32_t abase = sb + buf * GSTAGE_BYTES;
        const uint32_t bbase = abase + 16384;
#pragma unroll
        for (int kk = 0; kk < 4; kk++) {
            uint32_t af[2][4];
#pragma unroll
            for (int mi = 0; mi < 2; mi++) {
                const int row = a_row + mi * 16;
                const int ch = kk * 2 + a_chg;
                const int csw = ch ^ (row & 7);
                ldsm_x4(abase + row * 128 + csw * 16,
                        af[mi][0], af[mi][1], af[mi][2], af[mi][3]);
            }
            uint32_t bf[4][4];
#pragma unroll
            for (int nb = 0; nb < 4; nb++) {
                const int row = b_row + nb * 16;
                const int ch = kk * 2 + b_chg;
                const int csw = ch ^ (row & 7);
                ldsm_x4(bbase + row * 128 + csw * 16,
                        bf[nb][0], bf[nb][1], bf[nb][2], bf[nb][3]);
            }
#pragma unroll
            for (int mi = 0; mi < 2; mi++)
#pragma unroll
                for (int nb = 0; nb < 4; nb++) {
                    mma_bf16(acc[mi][nb * 2 + 0], af[mi], bf[nb][0], bf[nb][1]);
                    mma_bf16(acc[mi][nb * 2 + 1], af[mi], bf[nb][2], bf[nb][3]);
                }
        }
        buf = (buf + 1 == GSTAGES) ? 0 : buf + 1;
        nbuf = (nbuf + 1 == GSTAGES) ? 0 : nbuf + 1;
    }

    const int erow = (lane >> 2);
    const int ecol = (lane & 3) << 1;
#pragma unroll
    for (int mi = 0; mi < 2; mi++) {
        const int r = m0 + wm * 32 + mi * 16 + erow;
#pragma unroll
        for (int f = 0; f < 8; f++) {
            const int c = n0 + wn * 64 + (f >> 1) * 16 + (f & 1) * 8 + ecol;
            if (c < Nvalid) {
                *(float2*)(C + (size_t)r * Nstride + c) =
                    make_float2(acc[mi][f][0], acc[mi][f][1]);
                *(float2*)(C + (size_t)(r + 8) * Nstride + c) =
                    make_float2(acc[mi][f][2], acc[mi][f][3]);
            }
        }
    }
}

// -------- depthwise causal conv (K=4) + bias + silu, 8 t/thread --------
__global__ void conv_silu_kernel(const float* __restrict__ cw, const float* __restrict__ cb) {
    const int c = blockIdx.x * 256 + threadIdx.x;
    const int tb = blockIdx.y * 8;
    const float w0 = cw[c * 4 + 0], w1 = cw[c * 4 + 1],
                w2 = cw[c * 4 + 2], w3 = cw[c * 4 + 3];
    const float bias = cb[c];
    float v[11];
#pragma unroll
    for (int k = 0; k < 11; k++) {
        const int tt = tb - 3 + k;
        v[k] = (tt >= 0) ? g_proj[(size_t)tt * PROJD + INTERD + c] : 0.f;
    }
    if (c < INTERD) {
#pragma unroll
        for (int j = 0; j < 8; j++) {
            const float a = bias + v[j] * w0 + v[j + 1] * w1 + v[j + 2] * w2 + v[j + 3] * w3;
            g_hconv[(size_t)(tb + j) * CONVD + c] = a / (1.f + __expf(-a));
        }
    } else {
        const int cc = c - INTERD;
#pragma unroll
        for (int j = 0; j < 8; j++) {
            const float a = bias + v[j] * w0 + v[j + 1] * w1 + v[j + 2] * w2 + v[j + 3] * w3;
            const float y = a / (1.f + __expf(-a));
            const __nv_bfloat16 hb = __float2bfloat16(y);
            g_bch[(size_t)(tb + j) * BCW + cc] = hb;
            g_bcl[(size_t)(tb + j) * BCW + cc] =
                __float2bfloat16(y - __bfloat162float(hb));
        }
    }
}

// ---------------- fused softplus(dt)+cumsum per (chunk, head) ----------------
__global__ void dtacum_kernel(const float* __restrict__ dt_bias,
                              const float* __restrict__ A_log) {
    const int chunk = blockIdx.x;
    const int h = blockIdx.y;
    const int tid = threadIdx.x;
    const float Ah = -expf(A_log[h]);
    const float bias = dt_bias[h];
    __shared__ float s[CSZ];
    const int t = chunk * CSZ + tid;
    const float x = g_proj[(size_t)t * PROJD + DTOFF + h] + bias;
    const float dt2 = (x > 20.f) ? x : log1pf(expf(x));
    g_dt2[t * NH + h] = dt2;
    s[tid] = Ah * dt2;
    for (int off = 1; off < CSZ; off <<= 1) {
        __syncthreads();
        const float v = (tid >= off) ? s[tid - off] : 0.f;
        __syncthreads();
        s[tid] += v;
    }
    g_acum[h * SS + t] = s[tid];
}

// ================= SSD via HMMA, head-PAIRED (Gram shared per group) =================
// CTA per (chunk, head-pair within group): 8 warps x 32 i-rows, 4 j-tiles.
// Gram computed once per CTA per jt; weighted + stage2 per head (2 heads).
#define S_CHI 0
#define S_CLO 65536
#define S_GWH 131072
#define S_BHI 131072
#define S_BLO 147456
#define S_GWL 163840
#define S_XHI 196608
#define S_XLO 204800
#define S_ACS0 212992
#define S_ACS1 (212992 + 1024)
#define SSD_DYN_SMEM (212992 + 2048)

__device__ __forceinline__ void ssd_convert_x(char* sm, int tid, int t0, int jb, int h) {
#pragma unroll
    for (int it = 0; it < 4; it++) {
        const int u = it * 256 + tid;
        const int j = u >> 4;
        const int pb = (u & 15) * 4;
        const int tj = t0 + jb + j;
        float4 v = *(const float4*)(g_hconv + (size_t)tj * CONVD + h * HP + pb);
        const float sc = g_dt2[tj * NH + h];
        const float xv[4] = {v.x * sc, v.y * sc, v.z * sc, v.w * sc};
        const int wo = (j * 2) & 15;
        const int chn = j >> 3;
#pragma unroll
        for (int q = 0; q < 4; q++) {
            const int p = pb + q;
            const __nv_bfloat16 hb = __float2bfloat16(xv[q]);
            const __nv_bfloat16 lb = __float2bfloat16(xv[q] - __bfloat162float(hb));
            const uint32_t ad = p * 128 + ((chn ^ (p & 7)) << 4) + wo;
            *(__nv_bfloat16*)(sm + S_XHI + ad) = hb;
            *(__nv_bfloat16*)(sm + S_XLO + ad) = lb;
        }
    }
}

// weight Gram (kept intact in regs) with head's decay, store Gw hi/lo
__device__ __forceinline__ void ssd_store_gw(char* sm, const float (&g)[2][8][4],
                                             const float* acs, int i0, int ro, int co,
                                             int jb, float alast) {
#pragma unroll
    for (int mi = 0; mi < 2; mi++) {
        const int r1 = i0 + mi * 16 + ro;
        const int r2 = r1 + 8;
        const float a1 = acs[r1];
        const float a2 = acs[r2];
#pragma unroll
        for (int nb = 0; nb < 8; nb++) {
            const int c = (nb >> 1) * 16 + (nb & 1) * 8 + co;
            const int jg = jb + c;
            const float aj0 = acs[jg];
            const float aj1 = acs[jg + 1];
            // SAFE two-exp form: all evaluated-and-used exponents <= 0
            const float w00 = __expf(a1 - aj0 + alast) + ((jg     <= r1) ? __expf(a1 - aj0) : 0.f);
            const float w01 = __expf(a1 - aj1 + alast) + ((jg + 1 <= r1) ? __expf(a1 - aj1) : 0.f);
            const float w10 = __expf(a2 - aj0 + alast) + ((jg     <= r2) ? __expf(a2 - aj0) : 0.f);
            const float w11 = __expf(a2 - aj1 + alast) + ((jg + 1 <= r2) ? __expf(a2 - aj1) : 0.f);
            const float v0 = g[mi][nb][0] * w00;
            const float v1 = g[mi][nb][1] * w01;
            const float v2 = g[mi][nb][2] * w10;
            const float v3 = g[mi][nb][3] * w11;
            const int chn = c >> 3;
            const int wo = (c * 2) & 15;
            const uint32_t ad1 = r1 * 128 + ((chn ^ (r1 & 7)) << 4) + wo;
            const uint32_t ad2 = r2 * 128 + ((chn ^ (r2 & 7)) << 4) + wo;
            *(uint32_t*)(sm + S_GWH + ad1) = pack_bf2(v0, v1);
            *(uint32_t*)(sm + S_GWL + ad1) = pack_bf2(
                v0 - __bfloat162float(__float2bfloat16(v0)),
                v1 - __bfloat162float(__float2bfloat16(v1)));
            *(uint32_t*)(sm + S_GWH + ad2) = pack_bf2(v2, v3);
            *(uint32_t*)(sm + S_GWL + ad2) = pack_bf2(
                v2 - __bfloat162float(__float2bfloat16(v2)),
                v3 - __bfloat162float(__float2bfloat16(v3)));
        }
    }
}

__device__ __forceinline__ void ssd_stage2(uint32_t sb, int i0, int lane,
                                           float (&y)[2][8][4]) {
    for (int term = 0; term < 3; term++) {
        const uint32_t Ab = sb + ((term == 1) ? S_GWL : S_GWH);
        const uint32_t Bb = sb + ((term == 2) ? S_XLO : S_XHI);
#pragma unroll
        for (int ks = 0; ks < 4; ks++) {
            uint32_t af[2][4];
#pragma unroll
            for (int mi = 0; mi < 2; mi++) {
                const int row = i0 + mi * 16 + (lane & 15);
                const int ch = 2 * ks + (lane >> 4);
                const int csw = ch ^ (row & 7);
                ldsm_x4(Ab + row * 128 + csw * 16,
                        af[mi][0], af[mi][1], af[mi][2], af[mi][3]);
            }
#pragma unroll
            for (int q = 0; q < 4; q++) {
                const int bg = lane >> 3;
                const int brow = q * 16 + ((bg >> 1) << 3) + (lane & 7);
                const int bch = 2 * ks + (bg & 1);
                const int bcsw = bch ^ (brow & 7);
                uint32_t b0, b1, b2, b3;
                ldsm_x4(Bb + brow * 128 + bcsw * 16, b0, b1, b2, b3);
                mma_bf16(y[0][q * 2 + 0], af[0], b0, b1);
                mma_bf16(y[0][q * 2 + 1], af[0], b2, b3);
                mma_bf16(y[1][q * 2 + 0], af[1], b0, b1);
                mma_bf16(y[1][q * 2 + 1], af[1], b2, b3);
            }
        }
    }
}

__device__ __forceinline__ void ssd_epilogue(const float (&y)[2][8][4], int t0, int i0,
                                             int ro, int co, int h, float Dh) {
#pragma unroll
    for (int mi = 0; mi < 2; mi++) {
        const int r1 = t0 + i0 + mi * 16 + ro;
        const int r2 = r1 + 8;
#pragma unroll
        for (int nb = 0; nb < 8; nb++) {
            const int p = (nb >> 1) * 16 + (nb & 1) * 8 + co;
            const float2 h1 = *(const float2*)(g_hconv + (size_t)r1 * CONVD + h * HP + p);
            const float2 h2 = *(const float2*)(g_hconv + (size_t)r2 * CONVD + h * HP + p);
            *(float2*)(g_y + (size_t)r1 * INTERD + h * HP + p) =
                make_float2(y[mi][nb][0] + Dh * h1.x, y[mi][nb][1] + Dh * h1.y);
            *(float2*)(g_y + (size_t)r2 * INTERD + h * HP + p) =
                make_float2(y[mi][nb][2] + Dh * h2.x, y[mi][nb][3] + Dh * h2.y);
        }
    }
}

__global__ __launch_bounds__(256, 1)
void ssd_hmma(const float* __restrict__ Dp) {
    extern __shared__ char sm[];
    const uint32_t sb = smem_u32(sm);
    float* acs0 = (float*)(sm + S_ACS0);
    float* acs1 = (float*)(sm + S_ACS1);
    const int tid = threadIdx.x;
    const int lane = tid & 31;
    const int w = tid >> 5;
    const int chunk = blockIdx.x;
    const int grp = blockIdx.y & 7;
    const int pair = blockIdx.y >> 3;
    const int h0 = grp + pair * 16;
    const int h1 = h0 + 8;
    const int t0 = chunk * CSZ;
    const int Bcol = grp * SN;
    const int Ccol = NG * SN + grp * SN;
    const int i0 = w * 32;

    // C tile: 256 rows x 128 n bf16 hi/lo via cp.async (swizzled)
#pragma unroll 4
    for (int it = 0; it < 16; it++) {
        const int u = it * 256 + tid;
        const int i = u >> 4;
        const int nb = u & 15;
        const uint32_t dsw = i * 256 + ((nb ^ (i & 7)) << 4);
        const size_t gsrc = (size_t)(t0 + i) * BCW + Ccol + nb * 8;
        cp_async16(sb + S_CHI + dsw, g_bch + gsrc);
        cp_async16(sb + S_CLO + dsw, g_bcl + gsrc);
    }
    CP_COMMIT();

    acs0[tid] = g_acum[h0 * SS + t0 + tid];
    acs1[tid] = g_acum[h1 * SS + t0 + tid];

    float yacc0[2][8][4], yacc1[2][8][4];
#pragma unroll
    for (int mi = 0; mi < 2; mi++)
#pragma unroll
        for (int nb = 0; nb < 8; nb++)
#pragma unroll
            for (int q = 0; q < 4; q++) { yacc0[mi][nb][q] = 0.f; yacc1[mi][nb][q] = 0.f; }

    const int ro = lane >> 2;
    const int co = (lane & 3) * 2;

    for (int jt = 0; jt < 4; jt++) {
        const int jb = jt * 64;
        // B tile: 64 rows x 128 n bf16 hi/lo
#pragma unroll
        for (int it = 0; it < 4; it++) {
            const int u = it * 256 + tid;
            const int j = u >> 4;
            const int nb = u & 15;
            const uint32_t dsw = j * 256 + ((nb ^ (j & 7)) << 4);
            const size_t gsrc = (size_t)(t0 + jb + j) * BCW + Bcol + nb * 8;
            cp_async16(sb + S_BHI + dsw, g_bch + gsrc);
            cp_async16(sb + S_BLO + dsw, g_bcl + gsrc);
        }
        CP_COMMIT();
        ssd_convert_x(sm, tid, t0, jb, h0);
        asm volatile("cp.async.wait_group 0;" ::: "memory");
        __syncthreads();                                   // sync1: B/C/X0 ready

        const float alast0 = acs0[CSZ - 1];
        const float alast1 = acs1[CSZ - 1];

        // ---- stage 1: Gram (shared by both heads), K = 128 x 3 terms ----
        float gacc[2][8][4];
#pragma unroll
        for (int mi = 0; mi < 2; mi++)
#pragma unroll
            for (int nb = 0; nb < 8; nb++)
#pragma unroll
                for (int q = 0; q < 4; q++) gacc[mi][nb][q] = 0.f;

        for (int term = 0; term < 3; term++) {
            const uint32_t Ab = sb + ((term == 1) ? S_CLO : S_CHI);
            const uint32_t Bb = sb + ((term == 2) ? S_BLO : S_BHI);
#pragma unroll
            for (int ks = 0; ks < 8; ks++) {
                uint32_t af[2][4];
#pragma unroll
                for (int mi = 0; mi < 2; mi++) {
                    const int row = i0 + mi * 16 + (lane & 15);
                    const int ch = 2 * ks + (lane >> 4);
                    const int csw = ch ^ (row & 7);
                    ldsm_x4(Ab + row * 256 + csw * 16,
                            af[mi][0], af[mi][1], af[mi][2], af[mi][3]);
                }
#pragma unroll
                for (int q = 0; q < 4; q++) {
                    const int bg = lane >> 3;
                    const int brow = q * 16 + ((bg >> 1) << 3) + (lane & 7);
                    const int bch = 2 * ks + (bg & 1);
                    const int bcsw = bch ^ (brow & 7);
                    uint32_t b0, b1, b2, b3;
                    ldsm_x4(Bb + brow * 256 + bcsw * 16, b0, b1, b2, b3);
                    mma_bf16(gacc[0][q * 2 + 0], af[0], b0, b1);
                    mma_bf16(gacc[0][q * 2 + 1], af[0], b2, b3);
                    mma_bf16(gacc[1][q * 2 + 0], af[1], b0, b1);
                    mma_bf16(gacc[1][q * 2 + 1], af[1], b2, b3);
                }
            }
        }
        __syncthreads();                                   // sync2: B reads done
        ssd_store_gw(sm, gacc, acs0, i0, ro, co, jb, alast0);
        __syncthreads();                                   // sync3: Gw0 ready
        ssd_stage2(sb, i0, lane, yacc0);
        __syncthreads();                                   // sync4: stage2-h0 done
        ssd_convert_x(sm, tid, t0, jb, h1);
        ssd_store_gw(sm, gacc, acs1, i0, ro, co, jb, alast1);
        __syncthreads();                                   // sync5: Gw1/X1 ready
        ssd_stage2(sb, i0, lane, yacc1);
        __syncthreads();                                   // sync6: loop end
    }

    ssd_epilogue(yacc0, t0, i0, ro, co, h0, Dp[h0]);
    ssd_epilogue(yacc1, t0, i0, ro, co, h1, Dp[h1]);
}

// ---------------- gate silu + RMSNorm + split-bf16 A-pack (fused) ----------------
__global__ void norm_pack_kernel(const float* __restrict__ norm_w) {
    const int t = blockIdx.x;
    const int tid = threadIdx.x;
    __shared__ float red[256];
    __shared__ float yg_s[INTERD];
    float local = 0.f;
    for (int c = tid * 4; c < INTERD; c += 1024) {
        const float4 g4 = *(const float4*)(g_proj + (size_t)t * PROJD + c);
        const float4 y4 = *(const float4*)(g_y + (size_t)t * INTERD + c);
        const float yg0 = y4.x * (g4.x / (1.f + __expf(-g4.x)));
        const float yg1 = y4.y * (g4.y / (1.f + __expf(-g4.y)));
        const float yg2 = y4.z * (g4.z / (1.f + __expf(-g4.z)));
        const float yg3 = y4.w * (g4.w / (1.f + __expf(-g4.w)));
        *(float4*)(yg_s + c) = make_float4(yg0, yg1, yg2, yg3);
        local += yg0 * yg0 + yg1 * yg1 + yg2 * yg2 + yg3 * yg3;
    }
    red[tid] = local;
    __syncthreads();
    for (int s = 128; s > 0; s >>= 1) {
        if (tid < s) red[tid] += red[tid + s];
        __syncthreads();
    }
    const float rstd = rsqrtf(red[0] / (float)INTERD + 1e-6f);
    __nv_bfloat16* dst = g_Apack + (size_t)t * 3 * INTERD;
    for (int c = tid * 4; c < INTERD; c += 1024) {
        union { __nv_bfloat16 h[4]; uint2 u; } uh, ul;
#pragma unroll
        for (int i = 0; i < 4; i++) {
            const float v = norm_w[c + i] * yg_s[c + i] * rstd;
            uh.h[i] = __float2bfloat16(v);
            ul.h[i] = __float2bfloat16(v - __bfloat162float(uh.h[i]));
        }
        *(uint2*)(dst + c) = uh.u;
        *(uint2*)(dst + INTERD + c) = ul.u;
        *(uint2*)(dst + 2 * INTERD + c) = uh.u;
    }
}

// ---------------- launch ----------------
extern "C" void kernel_launch(void* const* d_in, const int* in_sizes, int n_in,
                              void* d_out, int out_size) {
    (void)in_sizes; (void)n_in; (void)out_size;
    const float* x       = (const float*)d_in[0];
    const float* w_in    = (const float*)d_in[1];
    const float* conv_w  = (const float*)d_in[2];
    const float* conv_b  = (const float*)d_in[3];
    const float* dt_bias = (const float*)d_in[4];
    const float* A_log   = (const float*)d_in[5];
    const float* Dv      = (const float*)d_in[6];
    const float* norm_w  = (const float*)d_in[7];
    const float* w_out   = (const float*)d_in[8];
    float* out = (float*)d_out;

    float* p_proj = nullptr;
    __nv_bfloat16* p_Apack = nullptr;
    __nv_bfloat16* p_B1 = nullptr;
    __nv_bfloat16* p_B2 = nullptr;
    cudaGetSymbolAddress((void**)&p_proj, g_proj);
    cudaGetSymbolAddress((void**)&p_Apack, g_Apack);
    cudaGetSymbolAddress((void**)&p_B1, g_B1);
    cudaGetSymbolAddress((void**)&p_B2, g_B2);

    cudaFuncSetAttribute(tgemm, cudaFuncAttributeMaxDynamicSharedMemorySize, GEMM_DYN_SMEM);
    cudaFuncSetAttribute(ssd_hmma, cudaFuncAttributeMaxDynamicSharedMemorySize, SSD_DYN_SMEM);

    // --- GEMM1 packs (split so tgemm is the 4th launch for ncu) ---
    pack_split<<<2048, 256>>>(x, p_Apack, SS, 0, SS, EMB, 0);
    pack_split<<<2048, 256>>>(w_in, p_B1, PROJD, 0, PROJPAD / 2, EMB, 1);
    pack_split<<<2048, 256>>>(w_in, p_B1, PROJD, PROJPAD / 2, PROJPAD, EMB, 1);
    // --- GEMM1: proj = X @ W_in^T ---
    tgemm<<<dim3(SS / 128, PROJPAD / 128), 256, GEMM_DYN_SMEM>>>(
        p_Apack, p_B1, p_proj, 3 * EMB, PROJD, PROJD);

    // --- elementwise / scan stages ---
    conv_silu_kernel<<<dim3(CONVD / 256, SS / 8), 256>>>(conv_w, conv_b);
    dtacum_kernel<<<dim3(NCH, NH), CSZ>>>(dt_bias, A_log);
    ssd_hmma<<<dim3(NCH, 32), 256, SSD_DYN_SMEM>>>(Dv);
    norm_pack_kernel<<<SS, 256>>>(norm_w);

    // --- GEMM2: out = normed @ W_out^T ---
    pack_split<<<2048, 256>>>(w_out, p_B2, EMB, 0, EMB, INTERD, 1);
    tgemm<<<dim3(SS / 128, EMB / 128), 256, GEMM_DYN_SMEM>>>(
        p_Apack, p_B2, out, 3 * INTERD, EMB, EMB);
}

// round 15
// speedup vs baseline: 1.0806x; 1.0370x over previous
#include <cuda_runtime.h>
#include <cuda_bf16.h>
#include <cstdint>
#include <cstddef>

// ---------------- problem constants ----------------
#define SS      4096
#define EMB     2048
#define PROJD   10304
#define PROJPAD 10368
#define INTERD  4096
#define CONVD   6144
#define NH      64
#define HP      64
#define SN      128
#define NG      8
#define CSZ     256
#define NCH     16
#define DTOFF   10240
#define BCW     2048

// ---------------- scratch ----------------
__device__ float g_proj[(size_t)SS * PROJD];
__device__ float g_hconv[(size_t)SS * CONVD];
__device__ float g_dt2[SS * NH];
__device__ float g_acum[NH * SS];
__device__ float g_y[(size_t)SS * INTERD];
__device__ __nv_bfloat16 g_bch[(size_t)SS * BCW];
__device__ __nv_bfloat16 g_bcl[(size_t)SS * BCW];
__device__ __nv_bfloat16 g_Apack[(size_t)SS * 3 * INTERD];
__device__ __nv_bfloat16 g_B1[(size_t)PROJPAD * 3 * EMB];
__device__ __nv_bfloat16 g_B2[(size_t)EMB * 3 * INTERD];

// ================= helpers =================
__device__ __forceinline__ uint32_t smem_u32(const void* p) {
    uint32_t a;
    asm("{ .reg .u64 t; cvta.to.shared.u64 t, %1; cvt.u32.u64 %0, t; }" : "=r"(a) : "l"(p));
    return a;
}
__device__ __forceinline__ void cp_async16(uint32_t saddr, const void* g) {
    asm volatile("cp.async.cg.shared.global [%0], [%1], 16;" :: "r"(saddr), "l"(g) : "memory");
}
#define CP_COMMIT() asm volatile("cp.async.commit_group;" ::: "memory")

__device__ __forceinline__ void ldsm_x4(uint32_t addr, uint32_t& r0, uint32_t& r1,
                                        uint32_t& r2, uint32_t& r3) {
    asm volatile("ldmatrix.sync.aligned.m8n8.x4.shared.b16 {%0,%1,%2,%3}, [%4];"
                 : "=r"(r0), "=r"(r1), "=r"(r2), "=r"(r3) : "r"(addr));
}
__device__ __forceinline__ void mma_bf16(float* d, const uint32_t* a, uint32_t b0, uint32_t b1) {
    asm volatile(
        "mma.sync.aligned.m16n8k16.row.col.f32.bf16.bf16.f32 "
        "{%0,%1,%2,%3}, {%4,%5,%6,%7}, {%8,%9}, {%0,%1,%2,%3};"
        : "+f"(d[0]), "+f"(d[1]), "+f"(d[2]), "+f"(d[3])
        : "r"(a[0]), "r"(a[1]), "r"(a[2]), "r"(a[3]), "r"(b0), "r"(b1));
}
__device__ __forceinline__ uint32_t pack_bf2(float x, float y) {
    __nv_bfloat16 a = __float2bfloat16(x);
    __nv_bfloat16 b = __float2bfloat16(y);
    return (uint32_t)__bfloat16_as_ushort(a) | ((uint32_t)__bfloat16_as_ushort(b) << 16);
}

// ================= split-pack core (3K storage) =================
// mode 0 (A): [hi | lo | hi]; mode 1 (B): [hi | hi | lo]
__device__ __forceinline__ void pack_core(
    const float* __restrict__ src, __nv_bfloat16* __restrict__ dst,
    int srcRows, int dstRows, int K, int mode, int vblk, int nblk) {
    const int K8 = K >> 3;
    const size_t total = (size_t)dstRows * K8;
    for (size_t v = (size_t)vblk * 256 + threadIdx.x; v < total;
         v += (size_t)nblk * 256) {
        const int r = (int)(v / K8);
        const int k = (int)(v % K8) << 3;
        float x[8];
        if (r < srcRows) {
            const float4 f0 = *(const float4*)(src + (size_t)r * K + k);
            const float4 f1 = *(const float4*)(src + (size_t)r * K + k + 4);
            x[0] = f0.x; x[1] = f0.y; x[2] = f0.z; x[3] = f0.w;
            x[4] = f1.x; x[5] = f1.y; x[6] = f1.z; x[7] = f1.w;
        } else {
#pragma unroll
            for (int i = 0; i < 8; i++) x[i] = 0.f;
        }
        union { __nv_bfloat16 h[8]; uint4 u; } uh, ul;
#pragma unroll
        for (int i = 0; i < 8; i++) {
            uh.h[i] = __float2bfloat16(x[i]);
            ul.h[i] = __float2bfloat16(x[i] - __bfloat162float(uh.h[i]));
        }
        const size_t ro = (size_t)r * 3 * K + k;
        *(uint4*)(dst + ro) = uh.u;
        if (mode == 0) {
            *(uint4*)(dst + ro + K) = ul.u;
            *(uint4*)(dst + ro + 2 * K) = uh.u;
        } else {
            *(uint4*)(dst + ro + K) = uh.u;
            *(uint4*)(dst + ro + 2 * K) = ul.u;
        }
    }
}

// ================= mega_pre: pack A + pack B1 in one grid =================
__global__ void mega_pre(const float* __restrict__ x, const float* __restrict__ w_in) {
    const int bid = blockIdx.x;
    if (bid < 2048) {
        pack_core(x, g_Apack, SS, SS, EMB, 0, bid, 2048);
    } else {
        pack_core(w_in, g_B1, PROJD, PROJPAD, EMB, 1, bid - 2048, 4096);
    }
}

// ================= HMMA GEMM (R10 exact): CTA 128x128, BK=64, 3-stage, 2 CTA/SM =====
#define GSTAGES 3
#define GSTAGE_BYTES 32768
#define GEMM_DYN_SMEM (GSTAGES * GSTAGE_BYTES)

__device__ __forceinline__ void gemm_load_stage(
    const __nv_bfloat16* __restrict__ A, const __nv_bfloat16* __restrict__ B,
    int K3, int m0, int n0, int tid, uint32_t sb, int stage, int kk) {
    const uint32_t abase = sb + stage * GSTAGE_BYTES;
    const uint32_t bbase = abase + 16384;
    const int k0 = kk * 64;
#pragma unroll
    for (int it = 0; it < 4; it++) {
        const int idx = it * 256 + tid;
        const int row = idx >> 3;
        const int ch = idx & 7;
        const int csw = ch ^ (row & 7);
        cp_async16(abase + row * 128 + csw * 16,
                   A + (size_t)(m0 + row) * K3 + k0 + ch * 8);
    }
#pragma unroll
    for (int it = 0; it < 4; it++) {
        const int idx = it * 256 + tid;
        const int row = idx >> 3;
        const int ch = idx & 7;
        const int csw = ch ^ (row & 7);
        cp_async16(bbase + row * 128 + csw * 16,
                   B + (size_t)(n0 + row) * K3 + k0 + ch * 8);
    }
}

__global__ __launch_bounds__(256, 2)
void tgemm(const __nv_bfloat16* __restrict__ A, const __nv_bfloat16* __restrict__ B,
           float* __restrict__ C, int K3, int Nvalid, int Nstride) {
    extern __shared__ char dynsm[];
    const uint32_t sb = smem_u32(dynsm);
    const int tid = threadIdx.x;
    const int lane = tid & 31;
    const int wid = tid >> 5;
    const int wm = wid & 3;
    const int wn = wid >> 2;

    const int gridM = gridDim.x;
    const int gridN = gridDim.y;
    const int bid = blockIdx.y * gridM + blockIdx.x;
    const int GM = 16;
    const int group = bid / (GM * gridN);
    const int rem = bid - group * (GM * gridN);
    const int m0 = (group * GM + (rem % GM)) * 128;
    const int n0 = (rem / GM) * 128;
    const int nK = K3 >> 6;

    float acc[2][8][4];
#pragma unroll
    for (int i = 0; i < 2; i++)
#pragma unroll
        for (int j = 0; j < 8; j++)
#pragma unroll
            for (int q = 0; q < 4; q++) acc[i][j][q] = 0.f;

    gemm_load_stage(A, B, K3, m0, n0, tid, sb, 0, 0); CP_COMMIT();
    gemm_load_stage(A, B, K3, m0, n0, tid, sb, 1, 1); CP_COMMIT();

    const int a_row = wm * 32 + (lane & 15);
    const int a_chg = lane >> 4;
    const int b_g = lane >> 3;
    const int b_row = wn * 64 + ((b_g >> 1) << 3) + (lane & 7);
    const int b_chg = b_g & 1;

    int buf = 0, nbuf = 2;
    for (int i = 0; i < nK; i++) {
        asm volatile("cp.async.wait_group 1;" ::: "memory");
        __syncthreads();
        if (i + 2 < nK) gemm_load_stage(A, B, K3, m0, n0, tid, sb, nbuf, i + 2);
        CP_COMMIT();

        const uint32_t abase = sb + buf * GSTAGE_BYTES;
        const uint32_t bbase = abase + 16384;
#pragma unroll
        for (int kk = 0; kk < 4; kk++) {
            uint32_t af[2][4];
#pragma unroll
            for (int mi = 0; mi < 2; mi++) {
                const int row = a_row + mi * 16;
                const int ch = kk * 2 + a_chg;
                const int csw = ch ^ (row & 7);
                ldsm_x4(abase + row * 128 + csw * 16,
                        af[mi][0], af[mi][1], af[mi][2], af[mi][3]);
            }
            uint32_t bf[4][4];
#pragma unroll
            for (int nb = 0; nb < 4; nb++) {
                const int row = b_row + nb * 16;
                const int ch = kk * 2 + b_chg;
                const int csw = ch ^ (row & 7);
                ldsm_x4(bbase + row * 128 + csw * 16,
                        bf[nb][0], bf[nb][1], bf[nb][2], bf[nb][3]);
            }
#pragma unroll
            for (int mi = 0; mi < 2; mi++)
#pragma unroll
                for (int nb = 0; nb < 4; nb++) {
                    mma_bf16(acc[mi][nb * 2 + 0], af[mi], bf[nb][0], bf[nb][1]);
                    mma_bf16(acc[mi][nb * 2 + 1], af[mi], bf[nb][2], bf[nb][3]);
                }
        }
        buf = (buf + 1 == GSTAGES) ? 0 : buf + 1;
        nbuf = (nbuf + 1 == GSTAGES) ? 0 : nbuf + 1;
    }

    const int erow = (lane >> 2);
    const int ecol = (lane & 3) << 1;
#pragma unroll
    for (int mi = 0; mi < 2; mi++) {
        const int r = m0 + wm * 32 + mi * 16 + erow;
#pragma unroll
        for (int f = 0; f < 8; f++) {
            const int c = n0 + wn * 64 + (f >> 1) * 16 + (f & 1) * 8 + ecol;
            if (c < Nvalid) {
                *(float2*)(C + (size_t)r * Nstride + c) =
                    make_float2(acc[mi][f][0], acc[mi][f][1]);
                *(float2*)(C + (size_t)(r + 8) * Nstride + c) =
                    make_float2(acc[mi][f][2], acc[mi][f][3]);
            }
        }
    }
}

// ================= mega_mid: conv_silu + dtacum + pack_B2 in one grid =================
// grid (30, 512): x<24 conv; x in [24,26) dtacum; x in [26,30) pack_B2
__global__ void mega_mid(const float* __restrict__ cw, const float* __restrict__ cb,
                         const float* __restrict__ dt_bias, const float* __restrict__ A_log,
                         const float* __restrict__ w_out) {
    __shared__ float s[CSZ];
    const int bx = blockIdx.x;
    const int by = blockIdx.y;
    const int tid = threadIdx.x;

    if (bx < 24) {
        // ---- depthwise causal conv (K=4) + bias + silu, 8 t/thread ----
        const int c = bx * 256 + tid;
        const int tb = by * 8;
        const float w0 = cw[c * 4 + 0], w1 = cw[c * 4 + 1],
                    w2 = cw[c * 4 + 2], w3 = cw[c * 4 + 3];
        const float bias = cb[c];
        float v[11];
#pragma unroll
        for (int k = 0; k < 11; k++) {
            const int tt = tb - 3 + k;
            v[k] = (tt >= 0) ? g_proj[(size_t)tt * PROJD + INTERD + c] : 0.f;
        }
        if (c < INTERD) {
#pragma unroll
            for (int j = 0; j < 8; j++) {
                const float a = bias + v[j] * w0 + v[j + 1] * w1 + v[j + 2] * w2 + v[j + 3] * w3;
                g_hconv[(size_t)(tb + j) * CONVD + c] = a / (1.f + __expf(-a));
            }
        } else {
            const int cc = c - INTERD;
#pragma unroll
            for (int j = 0; j < 8; j++) {
                const float a = bias + v[j] * w0 + v[j + 1] * w1 + v[j + 2] * w2 + v[j + 3] * w3;
                const float y = a / (1.f + __expf(-a));
                const __nv_bfloat16 hb = __float2bfloat16(y);
                g_bch[(size_t)(tb + j) * BCW + cc] = hb;
                g_bcl[(size_t)(tb + j) * BCW + cc] =
                    __float2bfloat16(y - __bfloat162float(hb));
            }
        }
    } else if (bx < 26) {
        // ---- fused softplus(dt)+cumsum per (chunk, head) ----
        const int d = (bx - 24) * 512 + by;     // 0..1023
        const int chunk = d >> 6;
        const int h = d & 63;
        const float Ah = -expf(A_log[h]);
        const float bias = dt_bias[h];
        const int t = chunk * CSZ + tid;
        const float x = g_proj[(size_t)t * PROJD + DTOFF + h] + bias;
        const float dt2 = (x > 20.f) ? x : log1pf(expf(x));
        g_dt2[t * NH + h] = dt2;
        s[tid] = Ah * dt2;
        for (int off = 1; off < CSZ; off <<= 1) {
            __syncthreads();
            const float v = (tid >= off) ? s[tid - off] : 0.f;
            __syncthreads();
            s[tid] += v;
        }
        g_acum[h * SS + t] = s[tid];
    } else {
        // ---- pack_B2: w_out -> g_B2 ----
        const int p = (bx - 26) * 512 + by;     // 0..2047
        pack_core(w_out, g_B2, EMB, EMB, INTERD, 1, p, 2048);
    }
}

// ================= SSD via HMMA (R10 exact) =================
#define S_CHI 0
#define S_CLO 65536
#define S_GWH 131072
#define S_BHI 131072
#define S_BLO 147456
#define S_GWL 163840
#define S_XHI 196608
#define S_XLO 204800
#define S_ACS 212992
#define SSD_DYN_SMEM (S_ACS + 1024)

__global__ __launch_bounds__(256, 1)
void ssd_hmma(const float* __restrict__ Dp) {
    extern __shared__ char sm[];
    const uint32_t sb = smem_u32(sm);
    float* acs = (float*)(sm + S_ACS);
    const int tid = threadIdx.x;
    const int lane = tid & 31;
    const int w = tid >> 5;
    const int chunk = blockIdx.x;
    const int h = blockIdx.y;
    const int t0 = chunk * CSZ;
    const int grp = h & 7;
    const int Bcol = grp * SN;
    const int Ccol = NG * SN + grp * SN;
    const int i0 = w * 32;

#pragma unroll 4
    for (int it = 0; it < 16; it++) {
        const int u = it * 256 + tid;
        const int i = u >> 4;
        const int nb = u & 15;
        const uint32_t dsw = i * 256 + ((nb ^ (i & 7)) << 4);
        const size_t gsrc = (size_t)(t0 + i) * BCW + Ccol + nb * 8;
        cp_async16(sb + S_CHI + dsw, g_bch + gsrc);
        cp_async16(sb + S_CLO + dsw, g_bcl + gsrc);
    }
    CP_COMMIT();

    acs[tid] = g_acum[h * SS + t0 + tid];

    float yacc[2][8][4];
#pragma unroll
    for (int mi = 0; mi < 2; mi++)
#pragma unroll
        for (int nb = 0; nb < 8; nb++)
#pragma unroll
            for (int q = 0; q < 4; q++) yacc[mi][nb][q] = 0.f;

    const int ro = lane >> 2;
    const int co = (lane & 3) * 2;

    for (int jt = 0; jt < 4; jt++) {
        const int jb = jt * 64;
#pragma unroll
        for (int it = 0; it < 4; it++) {
            const int u = it * 256 + tid;
            const int j = u >> 4;
            const int nb = u & 15;
            const uint32_t dsw = j * 256 + ((nb ^ (j & 7)) << 4);
            const size_t gsrc = (size_t)(t0 + jb + j) * BCW + Bcol + nb * 8;
            cp_async16(sb + S_BHI + dsw, g_bch + gsrc);
            cp_async16(sb + S_BLO + dsw, g_bcl + gsrc);
        }
        CP_COMMIT();
#pragma unroll
        for (int it = 0; it < 4; it++) {
            const int u = it * 256 + tid;
            const int j = u >> 4;
            const int pb = (u & 15) * 4;
            const int tj = t0 + jb + j;
            float4 v = *(const float4*)(g_hconv + (size_t)tj * CONVD + h * HP + pb);
            const float sc = g_dt2[tj * NH + h];
            const float xv[4] = {v.x * sc, v.y * sc, v.z * sc, v.w * sc};
            const int wo = (j * 2) & 15;
            const int chn = j >> 3;
#pragma unroll
            for (int q = 0; q < 4; q++) {
                const int p = pb + q;
                const __nv_bfloat16 hb = __float2bfloat16(xv[q]);
                const __nv_bfloat16 lb = __float2bfloat16(xv[q] - __bfloat162float(hb));
                const uint32_t ad = p * 128 + ((chn ^ (p & 7)) << 4) + wo;
                *(__nv_bfloat16*)(sm + S_XHI + ad) = hb;
                *(__nv_bfloat16*)(sm + S_XLO + ad) = lb;
            }
        }
        asm volatile("cp.async.wait_group 0;" ::: "memory");
        __syncthreads();

        const float alast = acs[CSZ - 1];

        float gacc[2][8][4];
#pragma unroll
        for (int mi = 0; mi < 2; mi++)
#pragma unroll
            for (int nb = 0; nb < 8; nb++)
#pragma unroll
                for (int q = 0; q < 4; q++) gacc[mi][nb][q] = 0.f;

        for (int term = 0; term < 3; term++) {
            const uint32_t Ab = sb + ((term == 1) ? S_CLO : S_CHI);
            const uint32_t Bb = sb + ((term == 2) ? S_BLO : S_BHI);
#pragma unroll
            for (int ks = 0; ks < 8; ks++) {
                uint32_t af[2][4];
#pragma unroll
                for (int mi = 0; mi < 2; mi++) {
                    const int row = i0 + mi * 16 + (lane & 15);
                    const int ch = 2 * ks + (lane >> 4);
                    const int csw = ch ^ (row & 7);
                    ldsm_x4(Ab + row * 256 + csw * 16,
                            af[mi][0], af[mi][1], af[mi][2], af[mi][3]);
                }
#pragma unroll
                for (int q = 0; q < 4; q++) {
                    const int bg = lane >> 3;
                    const int brow = q * 16 + ((bg >> 1) << 3) + (lane & 7);
                    const int bch = 2 * ks + (bg & 1);
                    const int bcsw = bch ^ (brow & 7);
                    uint32_t b0, b1, b2, b3;
                    ldsm_x4(Bb + brow * 256 + bcsw * 16, b0, b1, b2, b3);
                    mma_bf16(gacc[0][q * 2 + 0], af[0], b0, b1);
                    mma_bf16(gacc[0][q * 2 + 1], af[0], b2, b3);
                    mma_bf16(gacc[1][q * 2 + 0], af[1], b0, b1);
                    mma_bf16(gacc[1][q * 2 + 1], af[1], b2, b3);
                }
            }
        }

#pragma unroll
        for (int mi = 0; mi < 2; mi++) {
            const int r1 = i0 + mi * 16 + ro;
            const int r2 = r1 + 8;
            const float a1 = acs[r1];
            const float a2 = acs[r2];
#pragma unroll
            for (int nb = 0; nb < 8; nb++) {
                const int cb = (nb >> 1) * 16 + (nb & 1) * 8 + co;
                const int jg = jb + cb;
                const float aj0 = acs[jg];
                const float aj1 = acs[jg + 1];
                float wv;
                wv = __expf(a1 - aj0 + alast) + ((jg     <= r1) ? __expf(a1 - aj0) : 0.f);
                gacc[mi][nb][0] *= wv;
                wv = __expf(a1 - aj1 + alast) + ((jg + 1 <= r1) ? __expf(a1 - aj1) : 0.f);
                gacc[mi][nb][1] *= wv;
                wv = __expf(a2 - aj0 + alast) + ((jg     <= r2) ? __expf(a2 - aj0) : 0.f);
                gacc[mi][nb][2] *= wv;
                wv = __expf(a2 - aj1 + alast) + ((jg + 1 <= r2) ? __expf(a2 - aj1) : 0.f);
                gacc[mi][nb][3] *= wv;
            }
        }
        __syncthreads();

#pragma unroll
        for (int mi = 0; mi < 2; mi++) {
            const int r1 = i0 + mi * 16 + ro;
            const int r2 = r1 + 8;
#pragma unroll
            for (int nb = 0; nb < 8; nb++) {
                const int c = (nb >> 1) * 16 + (nb & 1) * 8 + co;
                const int chn = c >> 3;
                const int wo = (c * 2) & 15;
                const uint32_t ad1 = r1 * 128 + ((chn ^ (r1 & 7)) << 4) + wo;
                const uint32_t ad2 = r2 * 128 + ((chn ^ (r2 & 7)) << 4) + wo;
                *(uint32_t*)(sm + S_GWH + ad1) = pack_bf2(gacc[mi][nb][0], gacc[mi][nb][1]);
                *(uint32_t*)(sm + S_GWL + ad1) = pack_bf2(
                    gacc[mi][nb][0] - __bfloat162float(__float2bfloat16(gacc[mi][nb][0])),
                    gacc[mi][nb][1] - __bfloat162float(__float2bfloat16(gacc[mi][nb][1])));
                *(uint32_t*)(sm + S_GWH + ad2) = pack_bf2(gacc[mi][nb][2], gacc[mi][nb][3]);
                *(uint32_t*)(sm + S_GWL + ad2) = pack_bf2(
                    gacc[mi][nb][2] - __bfloat162float(__float2bfloat16(gacc[mi][nb][2])),
                    gacc[mi][nb][3] - __bfloat162float(__float2bfloat16(gacc[mi][nb][3])));
            }
        }
        __syncthreads();

        for (int term = 0; term < 3; term++) {
            const uint32_t Ab = sb + ((term == 1) ? S_GWL : S_GWH);
            const uint32_t Bb = sb + ((term == 2) ? S_XLO : S_XHI);
#pragma unroll
            for (int ks = 0; ks < 4; ks++) {
                uint32_t af[2][4];
#pragma unroll
                for (int mi = 0; mi < 2; mi++) {
                    const int row = i0 + mi * 16 + (lane & 15);
                    const int ch = 2 * ks + (lane >> 4);
                    const int csw = ch ^ (row & 7);
                    ldsm_x4(Ab + row * 128 + csw * 16,
                            af[mi][0], af[mi][1], af[mi][2], af[mi][3]);
                }
#pragma unroll
                for (int q = 0; q < 4; q++) {
                    const int bg = lane >> 3;
                    const int brow = q * 16 + ((bg >> 1) << 3) + (lane & 7);
                    const int bch = 2 * ks + (bg & 1);
                    const int bcsw = bch ^ (brow & 7);
                    uint32_t b0, b1, b2, b3;
                    ldsm_x4(Bb + brow * 128 + bcsw * 16, b0, b1, b2, b3);
                    mma_bf16(yacc[0][q * 2 + 0], af[0], b0, b1);
                    mma_bf16(yacc[0][q * 2 + 1], af[0], b2, b3);
                    mma_bf16(yacc[1][q * 2 + 0], af[1], b0, b1);
                    mma_bf16(yacc[1][q * 2 + 1], af[1], b2, b3);
                }
            }
        }
        __syncthreads();
    }

    const float Dh = Dp[h];
#pragma unroll
    for (int mi = 0; mi < 2; mi++) {
        const int r1 = t0 + i0 + mi * 16 + ro;
        const int r2 = r1 + 8;
#pragma unroll
        for (int nb = 0; nb < 8; nb++) {
            const int p = (nb >> 1) * 16 + (nb & 1) * 8 + co;
            const float2 h1 = *(const float2*)(g_hconv + (size_t)r1 * CONVD + h * HP + p);
            const float2 h2 = *(const float2*)(g_hconv + (size_t)r2 * CONVD + h * HP + p);
            *(float2*)(g_y + (size_t)r1 * INTERD + h * HP + p) =
                make_float2(yacc[mi][nb][0] + Dh * h1.x, yacc[mi][nb][1] + Dh * h1.y);
            *(float2*)(g_y + (size_t)r2 * INTERD + h * HP + p) =
                make_float2(yacc[mi][nb][2] + Dh * h2.x, yacc[mi][nb][3] + Dh * h2.y);
        }
    }
}

// ---------------- gate silu + RMSNorm + split-bf16 A-pack (fused) ----------------
__global__ void norm_pack_kernel(const float* __restrict__ norm_w) {
    const int t = blockIdx.x;
    const int tid = threadIdx.x;
    __shared__ float red[256];
    __shared__ float yg_s[INTERD];
    float local = 0.f;
    for (int c = tid * 4; c < INTERD; c += 1024) {
        const float4 g4 = *(const float4*)(g_proj + (size_t)t * PROJD + c);
        const float4 y4 = *(const float4*)(g_y + (size_t)t * INTERD + c);
        const float yg0 = y4.x * (g4.x / (1.f + __expf(-g4.x)));
        const float yg1 = y4.y * (g4.y / (1.f + __expf(-g4.y)));
        const float yg2 = y4.z * (g4.z / (1.f + __expf(-g4.z)));
        const float yg3 = y4.w * (g4.w / (1.f + __expf(-g4.w)));
        *(float4*)(yg_s + c) = make_float4(yg0, yg1, yg2, yg3);
        local += yg0 * yg0 + yg1 * yg1 + yg2 * yg2 + yg3 * yg3;
    }
    red[tid] = local;
    __syncthreads();
    for (int s = 128; s > 0; s >>= 1) {
        if (tid < s) red[tid] += red[tid + s];
        __syncthreads();
    }
    const float rstd = rsqrtf(red[0] / (float)INTERD + 1e-6f);
    __nv_bfloat16* dst = g_Apack + (size_t)t * 3 * INTERD;
    for (int c = tid * 4; c < INTERD; c += 1024) {
        union { __nv_bfloat16 h[4]; uint2 u; } uh, ul;
#pragma unroll
        for (int i = 0; i < 4; i++) {
            const float v = norm_w[c + i] * yg_s[c + i] * rstd;
            uh.h[i] = __float2bfloat16(v);
            ul.h[i] = __float2bfloat16(v - __bfloat162float(uh.h[i]));
        }
        *(uint2*)(dst + c) = uh.u;
        *(uint2*)(dst + INTERD + c) = ul.u;
        *(uint2*)(dst + 2 * INTERD + c) = uh.u;
    }
}

// ---------------- launch ----------------
extern "C" void kernel_launch(void* const* d_in, const int* in_sizes, int n_in,
                              void* d_out, int out_size) {
    (void)in_sizes; (void)n_in; (void)out_size;
    const float* x       = (const float*)d_in[0];
    const float* w_in    = (const float*)d_in[1];
    const float* conv_w  = (const float*)d_in[2];
    const float* conv_b  = (const float*)d_in[3];
    const float* dt_bias = (const float*)d_in[4];
    const float* A_log   = (const float*)d_in[5];
    const float* Dv      = (const float*)d_in[6];
    const float* norm_w  = (const float*)d_in[7];
    const float* w_out   = (const float*)d_in[8];
    float* out = (float*)d_out;

    float* p_proj = nullptr;
    __nv_bfloat16* p_Apack = nullptr;
    __nv_bfloat16* p_B1 = nullptr;
    __nv_bfloat16* p_B2 = nullptr;
    cudaGetSymbolAddress((void**)&p_proj, g_proj);
    cudaGetSymbolAddress((void**)&p_Apack, g_Apack);
    cudaGetSymbolAddress((void**)&p_B1, g_B1);
    cudaGetSymbolAddress((void**)&p_B2, g_B2);

    cudaFuncSetAttribute(tgemm, cudaFuncAttributeMaxDynamicSharedMemorySize, GEMM_DYN_SMEM);
    cudaFuncSetAttribute(ssd_hmma, cudaFuncAttributeMaxDynamicSharedMemorySize, SSD_DYN_SMEM);

    // 1) combined packs for GEMM1 (A + B1)
    mega_pre<<<6144, 256>>>(x, w_in);
    // 2) GEMM1: proj = X @ W_in^T
    tgemm<<<dim3(SS / 128, PROJPAD / 128), 256, GEMM_DYN_SMEM>>>(
        p_Apack, p_B1, p_proj, 3 * EMB, PROJD, PROJD);
    // 3) combined conv + dtacum + pack_B2
    mega_mid<<<dim3(30, 512), 256>>>(conv_w, conv_b, dt_bias, A_log, w_out);
    // 4) SSD
    ssd_hmma<<<dim3(NCH, NH), 256, SSD_DYN_SMEM>>>(Dv);
    // 5) gate + norm + A-pack
    norm_pack_kernel<<<SS, 256>>>(norm_w);
    // 6) GEMM2: out = normed @ W_out^T
    tgemm<<<dim3(SS / 128, EMB / 128), 256, GEMM_DYN_SMEM>>>(
        p_Apack, p_B2, out, 3 * INTERD, EMB, EMB);
}

// round 16
// speedup vs baseline: 1.0862x; 1.0052x over previous
#include <cuda_runtime.h>
#include <cuda_bf16.h>
#include <cstdint>
#include <cstddef>

// ---------------- problem constants ----------------
#define SS      4096
#define EMB     2048
#define PROJD   10304
#define PROJPAD 10368
#define INTERD  4096
#define CONVD   6144
#define NH      64
#define HP      64
#define SN      128
#define NG      8
#define CSZ     256
#define NCH     16
#define DTOFF   10240
#define BCW     2048

// ---------------- scratch ----------------
__device__ float g_proj[(size_t)SS * PROJD];
__device__ float g_hconv[(size_t)SS * CONVD];
__device__ float g_dt2[SS * NH];
__device__ float g_acum[NH * SS];
__device__ float g_y[(size_t)SS * INTERD];
__device__ __nv_bfloat16 g_bch[(size_t)SS * BCW];
__device__ __nv_bfloat16 g_bcl[(size_t)SS * BCW];
__device__ __nv_bfloat16 g_Apack[(size_t)SS * 3 * INTERD];
__device__ __nv_bfloat16 g_B1[(size_t)PROJPAD * 3 * EMB];
__device__ __nv_bfloat16 g_B2[(size_t)EMB * 3 * INTERD];

// ================= helpers =================
__device__ __forceinline__ uint32_t smem_u32(const void* p) {
    uint32_t a;
    asm("{ .reg .u64 t; cvta.to.shared.u64 t, %1; cvt.u32.u64 %0, t; }" : "=r"(a) : "l"(p));
    return a;
}
__device__ __forceinline__ void cp_async16(uint32_t saddr, const void* g) {
    asm volatile("cp.async.cg.shared.global [%0], [%1], 16;" :: "r"(saddr), "l"(g) : "memory");
}
#define CP_COMMIT() asm volatile("cp.async.commit_group;" ::: "memory")

__device__ __forceinline__ void ldsm_x4(uint32_t addr, uint32_t& r0, uint32_t& r1,
                                        uint32_t& r2, uint32_t& r3) {
    asm volatile("ldmatrix.sync.aligned.m8n8.x4.shared.b16 {%0,%1,%2,%3}, [%4];"
                 : "=r"(r0), "=r"(r1), "=r"(r2), "=r"(r3) : "r"(addr));
}
__device__ __forceinline__ void mma_bf16(float* d, const uint32_t* a, uint32_t b0, uint32_t b1) {
    asm volatile(
        "mma.sync.aligned.m16n8k16.row.col.f32.bf16.bf16.f32 "
        "{%0,%1,%2,%3}, {%4,%5,%6,%7}, {%8,%9}, {%0,%1,%2,%3};"
        : "+f"(d[0]), "+f"(d[1]), "+f"(d[2]), "+f"(d[3])
        : "r"(a[0]), "r"(a[1]), "r"(a[2]), "r"(a[3]), "r"(b0), "r"(b1));
}
__device__ __forceinline__ uint32_t pack_bf2(float x, float y) {
    __nv_bfloat16 a = __float2bfloat16(x);
    __nv_bfloat16 b = __float2bfloat16(y);
    return (uint32_t)__bfloat16_as_ushort(a) | ((uint32_t)__bfloat16_as_ushort(b) << 16);
}

// ================= split-pack core (3K storage) =================
// mode 0 (A): [hi | lo | hi]; mode 1 (B): [hi | hi | lo]
__device__ __forceinline__ void pack_core(
    const float* __restrict__ src, __nv_bfloat16* __restrict__ dst,
    int srcRows, int dstRows, int K, int mode, int vblk, int nblk) {
    const int K8 = K >> 3;
    const size_t total = (size_t)dstRows * K8;
    for (size_t v = (size_t)vblk * 256 + threadIdx.x; v < total;
         v += (size_t)nblk * 256) {
        const int r = (int)(v / K8);
        const int k = (int)(v % K8) << 3;
        float x[8];
        if (r < srcRows) {
            const float4 f0 = *(const float4*)(src + (size_t)r * K + k);
            const float4 f1 = *(const float4*)(src + (size_t)r * K + k + 4);
            x[0] = f0.x; x[1] = f0.y; x[2] = f0.z; x[3] = f0.w;
            x[4] = f1.x; x[5] = f1.y; x[6] = f1.z; x[7] = f1.w;
        } else {
#pragma unroll
            for (int i = 0; i < 8; i++) x[i] = 0.f;
        }
        union { __nv_bfloat16 h[8]; uint4 u; } uh, ul;
#pragma unroll
        for (int i = 0; i < 8; i++) {
            uh.h[i] = __float2bfloat16(x[i]);
            ul.h[i] = __float2bfloat16(x[i] - __bfloat162float(uh.h[i]));
        }
        const size_t ro = (size_t)r * 3 * K + k;
        *(uint4*)(dst + ro) = uh.u;
        if (mode == 0) {
            *(uint4*)(dst + ro + K) = ul.u;
            *(uint4*)(dst + ro + 2 * K) = uh.u;
        } else {
            *(uint4*)(dst + ro + K) = uh.u;
            *(uint4*)(dst + ro + 2 * K) = ul.u;
        }
    }
}

// ================= mega_pre: pack A + pack B1 in one grid =================
__global__ void mega_pre(const float* __restrict__ x, const float* __restrict__ w_in) {
    const int bid = blockIdx.x;
    if (bid < 2048) {
        pack_core(x, g_Apack, SS, SS, EMB, 0, bid, 2048);
    } else {
        pack_core(w_in, g_B1, PROJD, PROJPAD, EMB, 1, bid - 2048, 4096);
    }
}

// ================= HMMA GEMM (R10 exact): CTA 128x128, BK=64, 3-stage, 2 CTA/SM =====
#define GSTAGES 3
#define GSTAGE_BYTES 32768
#define GEMM_DYN_SMEM (GSTAGES * GSTAGE_BYTES)

__device__ __forceinline__ void gemm_load_stage(
    const __nv_bfloat16* __restrict__ A, const __nv_bfloat16* __restrict__ B,
    int K3, int m0, int n0, int tid, uint32_t sb, int stage, int kk) {
    const uint32_t abase = sb + stage * GSTAGE_BYTES;
    const uint32_t bbase = abase + 16384;
    const int k0 = kk * 64;
#pragma unroll
    for (int it = 0; it < 4; it++) {
        const int idx = it * 256 + tid;
        const int row = idx >> 3;
        const int ch = idx & 7;
        const int csw = ch ^ (row & 7);
        cp_async16(abase + row * 128 + csw * 16,
                   A + (size_t)(m0 + row) * K3 + k0 + ch * 8);
    }
#pragma unroll
    for (int it = 0; it < 4; it++) {
        const int idx = it * 256 + tid;
        const int row = idx >> 3;
        const int ch = idx & 7;
        const int csw = ch ^ (row & 7);
        cp_async16(bbase + row * 128 + csw * 16,
                   B + (size_t)(n0 + row) * K3 + k0 + ch * 8);
    }
}

__global__ __launch_bounds__(256, 2)
void tgemm(const __nv_bfloat16* __restrict__ A, const __nv_bfloat16* __restrict__ B,
           float* __restrict__ C, int K3, int Nvalid, int Nstride) {
    extern __shared__ char dynsm[];
    const uint32_t sb = smem_u32(dynsm);
    const int tid = threadIdx.x;
    const int lane = tid & 31;
    const int wid = tid >> 5;
    const int wm = wid & 3;
    const int wn = wid >> 2;

    const int gridM = gridDim.x;
    const int gridN = gridDim.y;
    const int bid = blockIdx.y * gridM + blockIdx.x;
    const int GM = 16;
    const int group = bid / (GM * gridN);
    const int rem = bid - group * (GM * gridN);
    const int m0 = (group * GM + (rem % GM)) * 128;
    const int n0 = (rem / GM) * 128;
    const int nK = K3 >> 6;

    float acc[2][8][4];
#pragma unroll
    for (int i = 0; i < 2; i++)
#pragma unroll
        for (int j = 0; j < 8; j++)
#pragma unroll
            for (int q = 0; q < 4; q++) acc[i][j][q] = 0.f;

    gemm_load_stage(A, B, K3, m0, n0, tid, sb, 0, 0); CP_COMMIT();
    gemm_load_stage(A, B, K3, m0, n0, tid, sb, 1, 1); CP_COMMIT();

    const int a_row = wm * 32 + (lane & 15);
    const int a_chg = lane >> 4;
    const int b_g = lane >> 3;
    const int b_row = wn * 64 + ((b_g >> 1) << 3) + (lane & 7);
    const int b_chg = b_g & 1;

    int buf = 0, nbuf = 2;
    for (int i = 0; i < nK; i++) {
        asm volatile("cp.async.wait_group 1;" ::: "memory");
        __syncthreads();
        if (i + 2 < nK) gemm_load_stage(A, B, K3, m0, n0, tid, sb, nbuf, i + 2);
        CP_COMMIT();

        const uint32_t abase = sb + buf * GSTAGE_BYTES;
        const uint32_t bbase = abase + 16384;
#pragma unroll
        for (int kk = 0; kk < 4; kk++) {
            uint32_t af[2][4];
#pragma unroll
            for (int mi = 0; mi < 2; mi++) {
                const int row = a_row + mi * 16;
                const int ch = kk * 2 + a_chg;
                const int csw = ch ^ (row & 7);
                ldsm_x4(abase + row * 128 + csw * 16,
                        af[mi][0], af[mi][1], af[mi][2], af[mi][3]);
            }
            uint32_t bf[4][4];
#pragma unroll
            for (int nb = 0; nb < 4; nb++) {
                const int row = b_row + nb * 16;
                const int ch = kk * 2 + b_chg;
                const int csw = ch ^ (row & 7);
                ldsm_x4(bbase + row * 128 + csw * 16,
                        bf[nb][0], bf[nb][1], bf[nb][2], bf[nb][3]);
            }
#pragma unroll
            for (int mi = 0; mi < 2; mi++)
#pragma unroll
                for (int nb = 0; nb < 4; nb++) {
                    mma_bf16(acc[mi][nb * 2 + 0], af[mi], bf[nb][0], bf[nb][1]);
                    mma_bf16(acc[mi][nb * 2 + 1], af[mi], bf[nb][2], bf[nb][3]);
                }
        }
        buf = (buf + 1 == GSTAGES) ? 0 : buf + 1;
        nbuf = (nbuf + 1 == GSTAGES) ? 0 : nbuf + 1;
    }

    const int erow = (lane >> 2);
    const int ecol = (lane & 3) << 1;
#pragma unroll
    for (int mi = 0; mi < 2; mi++) {
        const int r = m0 + wm * 32 + mi * 16 + erow;
#pragma unroll
        for (int f = 0; f < 8; f++) {
            const int c = n0 + wn * 64 + (f >> 1) * 16 + (f & 1) * 8 + ecol;
            if (c < Nvalid) {
                *(float2*)(C + (size_t)r * Nstride + c) =
                    make_float2(acc[mi][f][0], acc[mi][f][1]);
                *(float2*)(C + (size_t)(r + 8) * Nstride + c) =
                    make_float2(acc[mi][f][2], acc[mi][f][3]);
            }
        }
    }
}

// ================= mega_mid: conv_silu + dtacum + pack_B2 in one grid =================
// grid (30, 512): x<24 conv; x in [24,26) dtacum; x in [26,30) pack_B2
__global__ void mega_mid(const float* __restrict__ cw, const float* __restrict__ cb,
                         const float* __restrict__ dt_bias, const float* __restrict__ A_log,
                         const float* __restrict__ w_out) {
    __shared__ float s[CSZ];
    const int bx = blockIdx.x;
    const int by = blockIdx.y;
    const int tid = threadIdx.x;

    if (bx < 24) {
        const int c = bx * 256 + tid;
        const int tb = by * 8;
        const float w0 = cw[c * 4 + 0], w1 = cw[c * 4 + 1],
                    w2 = cw[c * 4 + 2], w3 = cw[c * 4 + 3];
        const float bias = cb[c];
        float v[11];
#pragma unroll
        for (int k = 0; k < 11; k++) {
            const int tt = tb - 3 + k;
            v[k] = (tt >= 0) ? g_proj[(size_t)tt * PROJD + INTERD + c] : 0.f;
        }
        if (c < INTERD) {
#pragma unroll
            for (int j = 0; j < 8; j++) {
                const float a = bias + v[j] * w0 + v[j + 1] * w1 + v[j + 2] * w2 + v[j + 3] * w3;
                g_hconv[(size_t)(tb + j) * CONVD + c] = a / (1.f + __expf(-a));
            }
        } else {
            const int cc = c - INTERD;
#pragma unroll
            for (int j = 0; j < 8; j++) {
                const float a = bias + v[j] * w0 + v[j + 1] * w1 + v[j + 2] * w2 + v[j + 3] * w3;
                const float y = a / (1.f + __expf(-a));
                const __nv_bfloat16 hb = __float2bfloat16(y);
                g_bch[(size_t)(tb + j) * BCW + cc] = hb;
                g_bcl[(size_t)(tb + j) * BCW + cc] =
                    __float2bfloat16(y - __bfloat162float(hb));
            }
        }
    } else if (bx < 26) {
        const int d = (bx - 24) * 512 + by;
        const int chunk = d >> 6;
        const int h = d & 63;
        const float Ah = -expf(A_log[h]);
        const float bias = dt_bias[h];
        const int t = chunk * CSZ + tid;
        const float x = g_proj[(size_t)t * PROJD + DTOFF + h] + bias;
        const float dt2 = (x > 20.f) ? x : log1pf(expf(x));
        g_dt2[t * NH + h] = dt2;
        s[tid] = Ah * dt2;
        for (int off = 1; off < CSZ; off <<= 1) {
            __syncthreads();
            const float v = (tid >= off) ? s[tid - off] : 0.f;
            __syncthreads();
            s[tid] += v;
        }
        g_acum[h * SS + t] = s[tid];
    } else {
        const int p = (bx - 26) * 512 + by;
        pack_core(w_out, g_B2, EMB, EMB, INTERD, 1, p, 2048);
    }
}

// ================= SSD via HMMA — relaxed barriers =================
// Gw-HI dedicated (no alias); Gw-LO aliases B region. Stage2 reads only the
// issuing warp's own rows -> syncwarp suffices between Gw store and stage2.
// Per j-tile: 3 __syncthreads instead of 4, and stage2 start is decoupled
// from other warps' Gw stores.
#define S_CHI 0
#define S_CLO 65536
#define S_BHI 131072
#define S_BLO 147456
#define S_GWL 131072          // aliases B (safe after post-stage1 barrier)
#define S_GWH 163840          // dedicated 32KB
#define S_XHI 196608
#define S_XLO 204800
#define S_ACS 212992
#define SSD_DYN_SMEM (S_ACS + 1024)

__global__ __launch_bounds__(256, 1)
void ssd_hmma(const float* __restrict__ Dp) {
    extern __shared__ char sm[];
    const uint32_t sb = smem_u32(sm);
    float* acs = (float*)(sm + S_ACS);
    const int tid = threadIdx.x;
    const int lane = tid & 31;
    const int w = tid >> 5;
    const int chunk = blockIdx.x;
    const int h = blockIdx.y;
    const int t0 = chunk * CSZ;
    const int grp = h & 7;
    const int Bcol = grp * SN;
    const int Ccol = NG * SN + grp * SN;
    const int i0 = w * 32;

#pragma unroll 4
    for (int it = 0; it < 16; it++) {
        const int u = it * 256 + tid;
        const int i = u >> 4;
        const int nb = u & 15;
        const uint32_t dsw = i * 256 + ((nb ^ (i & 7)) << 4);
        const size_t gsrc = (size_t)(t0 + i) * BCW + Ccol + nb * 8;
        cp_async16(sb + S_CHI + dsw, g_bch + gsrc);
        cp_async16(sb + S_CLO + dsw, g_bcl + gsrc);
    }
    CP_COMMIT();

    acs[tid] = g_acum[h * SS + t0 + tid];

    float yacc[2][8][4];
#pragma unroll
    for (int mi = 0; mi < 2; mi++)
#pragma unroll
        for (int nb = 0; nb < 8; nb++)
#pragma unroll
            for (int q = 0; q < 4; q++) yacc[mi][nb][q] = 0.f;

    const int ro = lane >> 2;
    const int co = (lane & 3) * 2;

    for (int jt = 0; jt < 4; jt++) {
        const int jb = jt * 64;
        // B tile loads (region also holds prev Gw-lo; prev stage2 done per loop-end sync)
#pragma unroll
        for (int it = 0; it < 4; it++) {
            const int u = it * 256 + tid;
            const int j = u >> 4;
            const int nb = u & 15;
            const uint32_t dsw = j * 256 + ((nb ^ (j & 7)) << 4);
            const size_t gsrc = (size_t)(t0 + jb + j) * BCW + Bcol + nb * 8;
            cp_async16(sb + S_BHI + dsw, g_bch + gsrc);
            cp_async16(sb + S_BLO + dsw, g_bcl + gsrc);
        }
        CP_COMMIT();
        // X convert (hid*dt2), TRANSPOSED [p][j]
#pragma unroll
        for (int it = 0; it < 4; it++) {
            const int u = it * 256 + tid;
            const int j = u >> 4;
            const int pb = (u & 15) * 4;
            const int tj = t0 + jb + j;
            float4 v = *(const float4*)(g_hconv + (size_t)tj * CONVD + h * HP + pb);
            const float sc = g_dt2[tj * NH + h];
            const float xv[4] = {v.x * sc, v.y * sc, v.z * sc, v.w * sc};
            const int wo = (j * 2) & 15;
            const int chn = j >> 3;
#pragma unroll
            for (int q = 0; q < 4; q++) {
                const int p = pb + q;
                const __nv_bfloat16 hb = __float2bfloat16(xv[q]);
                const __nv_bfloat16 lb = __float2bfloat16(xv[q] - __bfloat162float(hb));
                const uint32_t ad = p * 128 + ((chn ^ (p & 7)) << 4) + wo;
                *(__nv_bfloat16*)(sm + S_XHI + ad) = hb;
                *(__nv_bfloat16*)(sm + S_XLO + ad) = lb;
            }
        }
        asm volatile("cp.async.wait_group 0;" ::: "memory");
        __syncthreads();                      // sync1: B/C/X visible to all

        const float alast = acs[CSZ - 1];

        // ---- stage 1: Gram (own 32 i-rows x all 64 j), K = 128 x 3 terms ----
        float gacc[2][8][4];
#pragma unroll
        for (int mi = 0; mi < 2; mi++)
#pragma unroll
            for (int nb = 0; nb < 8; nb++)
#pragma unroll
                for (int q = 0; q < 4; q++) gacc[mi][nb][q] = 0.f;

        for (int term = 0; term < 3; term++) {
            const uint32_t Ab = sb + ((term == 1) ? S_CLO : S_CHI);
            const uint32_t Bb = sb + ((term == 2) ? S_BLO : S_BHI);
#pragma unroll
            for (int ks = 0; ks < 8; ks++) {
                uint32_t af[2][4];
#pragma unroll
                for (int mi = 0; mi < 2; mi++) {
                    const int row = i0 + mi * 16 + (lane & 15);
                    const int ch = 2 * ks + (lane >> 4);
                    const int csw = ch ^ (row & 7);
                    ldsm_x4(Ab + row * 256 + csw * 16,
                            af[mi][0], af[mi][1], af[mi][2], af[mi][3]);
                }
#pragma unroll
                for (int q = 0; q < 4; q++) {
                    const int bg = lane >> 3;
                    const int brow = q * 16 + ((bg >> 1) << 3) + (lane & 7);
                    const int bch = 2 * ks + (bg & 1);
                    const int bcsw = bch ^ (brow & 7);
                    uint32_t b0, b1, b2, b3;
                    ldsm_x4(Bb + brow * 256 + bcsw * 16, b0, b1, b2, b3);
                    mma_bf16(gacc[0][q * 2 + 0], af[0], b0, b1);
                    mma_bf16(gacc[0][q * 2 + 1], af[0], b2, b3);
                    mma_bf16(gacc[1][q * 2 + 0], af[1], b0, b1);
                    mma_bf16(gacc[1][q * 2 + 1], af[1], b2, b3);
                }
            }
        }

        // ---- weight in-place (SAFE two-exp form) + store Gw-HI (dedicated) ----
#pragma unroll
        for (int mi = 0; mi < 2; mi++) {
            const int r1 = i0 + mi * 16 + ro;
            const int r2 = r1 + 8;
            const float a1 = acs[r1];
            const float a2 = acs[r2];
#pragma unroll
            for (int nb = 0; nb < 8; nb++) {
                const int cb = (nb >> 1) * 16 + (nb & 1) * 8 + co;
                const int jg = jb + cb;
                const float aj0 = acs[jg];
                const float aj1 = acs[jg + 1];
                float wv;
                wv = __expf(a1 - aj0 + alast) + ((jg     <= r1) ? __expf(a1 - aj0) : 0.f);
                gacc[mi][nb][0] *= wv;
                wv = __expf(a1 - aj1 + alast) + ((jg + 1 <= r1) ? __expf(a1 - aj1) : 0.f);
                gacc[mi][nb][1] *= wv;
                wv = __expf(a2 - aj0 + alast) + ((jg     <= r2) ? __expf(a2 - aj0) : 0.f);
                gacc[mi][nb][2] *= wv;
                wv = __expf(a2 - aj1 + alast) + ((jg + 1 <= r2) ? __expf(a2 - aj1) : 0.f);
                gacc[mi][nb][3] *= wv;
                // Gw-HI store (dedicated region; no cross-warp hazard)
                const int chn = cb >> 3;
                const int wo = (cb * 2) & 15;
                const uint32_t ad1 = r1 * 128 + ((chn ^ (r1 & 7)) << 4) + wo;
                const uint32_t ad2 = r2 * 128 + ((chn ^ (r2 & 7)) << 4) + wo;
                *(uint32_t*)(sm + S_GWH + ad1) = pack_bf2(gacc[mi][nb][0], gacc[mi][nb][1]);
                *(uint32_t*)(sm + S_GWH + ad2) = pack_bf2(gacc[mi][nb][2], gacc[mi][nb][3]);
            }
        }
        __syncthreads();                      // sync2: all stage1 B reads done

        // ---- store Gw-LO (aliases B region, now safe) ----
#pragma unroll
        for (int mi = 0; mi < 2; mi++) {
            const int r1 = i0 + mi * 16 + ro;
            const int r2 = r1 + 8;
#pragma unroll
            for (int nb = 0; nb < 8; nb++) {
                const int c = (nb >> 1) * 16 + (nb & 1) * 8 + co;
                const int chn = c >> 3;
                const int wo = (c * 2) & 15;
                const uint32_t ad1 = r1 * 128 + ((chn ^ (r1 & 7)) << 4) + wo;
                const uint32_t ad2 = r2 * 128 + ((chn ^ (r2 & 7)) << 4) + wo;
                *(uint32_t*)(sm + S_GWL + ad1) = pack_bf2(
                    gacc[mi][nb][0] - __bfloat162float(__float2bfloat16(gacc[mi][nb][0])),
                    gacc[mi][nb][1] - __bfloat162float(__float2bfloat16(gacc[mi][nb][1])));
                *(uint32_t*)(sm + S_GWL + ad2) = pack_bf2(
                    gacc[mi][nb][2] - __bfloat162float(__float2bfloat16(gacc[mi][nb][2])),
                    gacc[mi][nb][3] - __bfloat162float(__float2bfloat16(gacc[mi][nb][3])));
            }
        }
        __syncwarp();                         // own-warp STS -> ldsm ordering only

        // ---- stage 2: Y += Gw @ X^T (reads ONLY own warp's Gw rows + X) ----
        for (int term = 0; term < 3; term++) {
            const uint32_t Ab = sb + ((term == 1) ? S_GWL : S_GWH);
            const uint32_t Bb = sb + ((term == 2) ? S_XLO : S_XHI);
#pragma unroll
            for (int ks = 0; ks < 4; ks++) {
                uint32_t af[2][4];
#pragma unroll
                for (int mi = 0; mi < 2; mi++) {
                    const int row = i0 + mi * 16 + (lane & 15);
                    const int ch = 2 * ks + (lane >> 4);
                    const int csw = ch ^ (row & 7);
                    ldsm_x4(Ab + row * 128 + csw * 16,
                            af[mi][0], af[mi][1], af[mi][2], af[mi][3]);
                }
#pragma unroll
                for (int q = 0; q < 4; q++) {
                    const int bg = lane >> 3;
                    const int brow = q * 16 + ((bg >> 1) << 3) + (lane & 7);
                    const int bch = 2 * ks + (bg & 1);
                    const int bcsw = bch ^ (brow & 7);
                    uint32_t b0, b1, b2, b3;
                    ldsm_x4(Bb + brow * 128 + bcsw * 16, b0, b1, b2, b3);
                    mma_bf16(yacc[0][q * 2 + 0], af[0], b0, b1);
                    mma_bf16(yacc[0][q * 2 + 1], af[0], b2, b3);
                    mma_bf16(yacc[1][q * 2 + 0], af[1], b0, b1);
                    mma_bf16(yacc[1][q * 2 + 1], af[1], b2, b3);
                }
            }
        }
        __syncthreads();                      // sync3: end of jt (protect B/X/Gw)
    }

    const float Dh = Dp[h];
#pragma unroll
    for (int mi = 0; mi < 2; mi++) {
        const int r1 = t0 + i0 + mi * 16 + ro;
        const int r2 = r1 + 8;
#pragma unroll
        for (int nb = 0; nb < 8; nb++) {
            const int p = (nb >> 1) * 16 + (nb & 1) * 8 + co;
            const float2 h1 = *(const float2*)(g_hconv + (size_t)r1 * CONVD + h * HP + p);
            const float2 h2 = *(const float2*)(g_hconv + (size_t)r2 * CONVD + h * HP + p);
            *(float2*)(g_y + (size_t)r1 * INTERD + h * HP + p) =
                make_float2(yacc[mi][nb][0] + Dh * h1.x, yacc[mi][nb][1] + Dh * h1.y);
            *(float2*)(g_y + (size_t)r2 * INTERD + h * HP + p) =
                make_float2(yacc[mi][nb][2] + Dh * h2.x, yacc[mi][nb][3] + Dh * h2.y);
        }
    }
}

// ---------------- gate silu + RMSNorm + split-bf16 A-pack (fused) ----------------
__global__ void norm_pack_kernel(const float* __restrict__ norm_w) {
    const int t = blockIdx.x;
    const int tid = threadIdx.x;
    __shared__ float red[256];
    __shared__ float yg_s[INTERD];
    float local = 0.f;
    for (int c = tid * 4; c < INTERD; c += 1024) {
        const float4 g4 = *(const float4*)(g_proj + (size_t)t * PROJD + c);
        const float4 y4 = *(const float4*)(g_y + (size_t)t * INTERD + c);
        const float yg0 = y4.x * (g4.x / (1.f + __expf(-g4.x)));
        const float yg1 = y4.y * (g4.y / (1.f + __expf(-g4.y)));
        const float yg2 = y4.z * (g4.z / (1.f + __expf(-g4.z)));
        const float yg3 = y4.w * (g4.w / (1.f + __expf(-g4.w)));
        *(float4*)(yg_s + c) = make_float4(yg0, yg1, yg2, yg3);
        local += yg0 * yg0 + yg1 * yg1 + yg2 * yg2 + yg3 * yg3;
    }
    red[tid] = local;
    __syncthreads();
    for (int s = 128; s > 0; s >>= 1) {
        if (tid < s) red[tid] += red[tid + s];
        __syncthreads();
    }
    const float rstd = rsqrtf(red[0] / (float)INTERD + 1e-6f);
    __nv_bfloat16* dst = g_Apack + (size_t)t * 3 * INTERD;
    for (int c = tid * 4; c < INTERD; c += 1024) {
        union { __nv_bfloat16 h[4]; uint2 u; } uh, ul;
#pragma unroll
        for (int i = 0; i < 4; i++) {
            const float v = norm_w[c + i] * yg_s[c + i] * rstd;
            uh.h[i] = __float2bfloat16(v);
            ul.h[i] = __float2bfloat16(v - __bfloat162float(uh.h[i]));
        }
        *(uint2*)(dst + c) = uh.u;
        *(uint2*)(dst + INTERD + c) = ul.u;
        *(uint2*)(dst + 2 * INTERD + c) = uh.u;
    }
}

// ---------------- launch ----------------
extern "C" void kernel_launch(void* const* d_in, const int* in_sizes, int n_in,
                              void* d_out, int out_size) {
    (void)in_sizes; (void)n_in; (void)out_size;
    const float* x       = (const float*)d_in[0];
    const float* w_in    = (const float*)d_in[1];
    const float* conv_w  = (const float*)d_in[2];
    const float* conv_b  = (const float*)d_in[3];
    const float* dt_bias = (const float*)d_in[4];
    const float* A_log   = (const float*)d_in[5];
    const float* Dv      = (const float*)d_in[6];
    const float* norm_w  = (const float*)d_in[7];
    const float* w_out   = (const float*)d_in[8];
    float* out = (float*)d_out;

    float* p_proj = nullptr;
    __nv_bfloat16* p_Apack = nullptr;
    __nv_bfloat16* p_B1 = nullptr;
    __nv_bfloat16* p_B2 = nullptr;
    cudaGetSymbolAddress((void**)&p_proj, g_proj);
    cudaGetSymbolAddress((void**)&p_Apack, g_Apack);
    cudaGetSymbolAddress((void**)&p_B1, g_B1);
    cudaGetSymbolAddress((void**)&p_B2, g_B2);

    cudaFuncSetAttribute(tgemm, cudaFuncAttributeMaxDynamicSharedMemorySize, GEMM_DYN_SMEM);
    cudaFuncSetAttribute(ssd_hmma, cudaFuncAttributeMaxDynamicSharedMemorySize, SSD_DYN_SMEM);

    // 1) combined packs for GEMM1 (A + B1)
    mega_pre<<<6144, 256>>>(x, w_in);
    // 2) GEMM1: proj = X @ W_in^T
    tgemm<<<dim3(SS / 128, PROJPAD / 128), 256, GEMM_DYN_SMEM>>>(
        p_Apack, p_B1, p_proj, 3 * EMB, PROJD, PROJD);
    // 3) combined conv + dtacum + pack_B2
    mega_mid<<<dim3(30, 512), 256>>>(conv_w, conv_b, dt_bias, A_log, w_out);
    // 4) SSD
    ssd_hmma<<<dim3(NCH, NH), 256, SSD_DYN_SMEM>>>(Dv);
    // 5) gate + norm + A-pack
    norm_pack_kernel<<<SS, 256>>>(norm_w);
    // 6) GEMM2: out = normed @ W_out^T
    tgemm<<<dim3(SS / 128, EMB / 128), 256, GEMM_DYN_SMEM>>>(
        p_Apack, p_B2, out, 3 * INTERD, EMB, EMB);
}

// round 17
// speedup vs baseline: 1.0977x; 1.0105x over previous
#include <cuda_runtime.h>
#include <cuda_bf16.h>
#include <cstdint>
#include <cstddef>

// ---------------- problem constants ----------------
#define SS      4096
#define EMB     2048
#define PROJD   10304
#define PROJPAD 10368
#define INTERD  4096
#define CONVD   6144
#define NH      64
#define HP      64
#define SN      128
#define NG      8
#define CSZ     256
#define NCH     16
#define DTOFF   10240
#define BCW     2048

// ---------------- scratch ----------------
__device__ float g_proj[(size_t)SS * PROJD];
__device__ float g_hconv[(size_t)SS * CONVD];
__device__ float g_dt2[SS * NH];
__device__ float g_acum[NH * SS];
__device__ float g_y[(size_t)SS * INTERD];
__device__ __nv_bfloat16 g_bch[(size_t)SS * BCW];
__device__ __nv_bfloat16 g_bcl[(size_t)SS * BCW];
__device__ __nv_bfloat16 g_Apack[(size_t)SS * 3 * INTERD];
__device__ __nv_bfloat16 g_B1[(size_t)PROJPAD * 3 * EMB];
__device__ __nv_bfloat16 g_B2[(size_t)EMB * 3 * INTERD];

// ================= helpers =================
__device__ __forceinline__ uint32_t smem_u32(const void* p) {
    uint32_t a;
    asm("{ .reg .u64 t; cvta.to.shared.u64 t, %1; cvt.u32.u64 %0, t; }" : "=r"(a) : "l"(p));
    return a;
}
__device__ __forceinline__ void cp_async16(uint32_t saddr, const void* g) {
    asm volatile("cp.async.cg.shared.global [%0], [%1], 16;" :: "r"(saddr), "l"(g) : "memory");
}
#define CP_COMMIT() asm volatile("cp.async.commit_group;" ::: "memory")

__device__ __forceinline__ void ldsm_x4(uint32_t addr, uint32_t& r0, uint32_t& r1,
                                        uint32_t& r2, uint32_t& r3) {
    asm volatile("ldmatrix.sync.aligned.m8n8.x4.shared.b16 {%0,%1,%2,%3}, [%4];"
                 : "=r"(r0), "=r"(r1), "=r"(r2), "=r"(r3) : "r"(addr));
}
__device__ __forceinline__ void mma_bf16(float* d, const uint32_t* a, uint32_t b0, uint32_t b1) {
    asm volatile(
        "mma.sync.aligned.m16n8k16.row.col.f32.bf16.bf16.f32 "
        "{%0,%1,%2,%3}, {%4,%5,%6,%7}, {%8,%9}, {%0,%1,%2,%3};"
        : "+f"(d[0]), "+f"(d[1]), "+f"(d[2]), "+f"(d[3])
        : "r"(a[0]), "r"(a[1]), "r"(a[2]), "r"(a[3]), "r"(b0), "r"(b1));
}
__device__ __forceinline__ uint32_t pack_bf2(float x, float y) {
    __nv_bfloat16 a = __float2bfloat16(x);
    __nv_bfloat16 b = __float2bfloat16(y);
    return (uint32_t)__bfloat16_as_ushort(a) | ((uint32_t)__bfloat16_as_ushort(b) << 16);
}
__device__ __forceinline__ float bf16_res(float x) {
    return x - __bfloat162float(__float2bfloat16(x));
}

// ================= split-pack core (3K storage) =================
__device__ __forceinline__ void pack_core(
    const float* __restrict__ src, __nv_bfloat16* __restrict__ dst,
    int srcRows, int dstRows, int K, int mode, int vblk, int nblk) {
    const int K8 = K >> 3;
    const size_t total = (size_t)dstRows * K8;
    for (size_t v = (size_t)vblk * 256 + threadIdx.x; v < total;
         v += (size_t)nblk * 256) {
        const int r = (int)(v / K8);
        const int k = (int)(v % K8) << 3;
        float x[8];
        if (r < srcRows) {
            const float4 f0 = *(const float4*)(src + (size_t)r * K + k);
            const float4 f1 = *(const float4*)(src + (size_t)r * K + k + 4);
            x[0] = f0.x; x[1] = f0.y; x[2] = f0.z; x[3] = f0.w;
            x[4] = f1.x; x[5] = f1.y; x[6] = f1.z; x[7] = f1.w;
        } else {
#pragma unroll
            for (int i = 0; i < 8; i++) x[i] = 0.f;
        }
        union { __nv_bfloat16 h[8]; uint4 u; } uh, ul;
#pragma unroll
        for (int i = 0; i < 8; i++) {
            uh.h[i] = __float2bfloat16(x[i]);
            ul.h[i] = __float2bfloat16(x[i] - __bfloat162float(uh.h[i]));
        }
        const size_t ro = (size_t)r * 3 * K + k;
        *(uint4*)(dst + ro) = uh.u;
        if (mode == 0) {
            *(uint4*)(dst + ro + K) = ul.u;
            *(uint4*)(dst + ro + 2 * K) = uh.u;
        } else {
            *(uint4*)(dst + ro + K) = uh.u;
            *(uint4*)(dst + ro + 2 * K) = ul.u;
        }
    }
}

// ================= mega_pre: pack A + pack B1 in one grid =================
__global__ void mega_pre(const float* __restrict__ x, const float* __restrict__ w_in) {
    const int bid = blockIdx.x;
    if (bid < 2048) {
        pack_core(x, g_Apack, SS, SS, EMB, 0, bid, 2048);
    } else {
        pack_core(w_in, g_B1, PROJD, PROJPAD, EMB, 1, bid - 2048, 4096);
    }
}

// ================= HMMA GEMM (frozen): CTA 128x128, BK=64, 3-stage, 2 CTA/SM =====
#define GSTAGES 3
#define GSTAGE_BYTES 32768
#define GEMM_DYN_SMEM (GSTAGES * GSTAGE_BYTES)

__device__ __forceinline__ void gemm_load_stage(
    const __nv_bfloat16* __restrict__ A, const __nv_bfloat16* __restrict__ B,
    int K3, int m0, int n0, int tid, uint32_t sb, int stage, int kk) {
    const uint32_t abase = sb + stage * GSTAGE_BYTES;
    const uint32_t bbase = abase + 16384;
    const int k0 = kk * 64;
#pragma unroll
    for (int it = 0; it < 4; it++) {
        const int idx = it * 256 + tid;
        const int row = idx >> 3;
        const int ch = idx & 7;
        const int csw = ch ^ (row & 7);
        cp_async16(abase + row * 128 + csw * 16,
                   A + (size_t)(m0 + row) * K3 + k0 + ch * 8);
    }
#pragma unroll
    for (int it = 0; it < 4; it++) {
        const int idx = it * 256 + tid;
        const int row = idx >> 3;
        const int ch = idx & 7;
        const int csw = ch ^ (row & 7);
        cp_async16(bbase + row * 128 + csw * 16,
                   B + (size_t)(n0 + row) * K3 + k0 + ch * 8);
    }
}

__global__ __launch_bounds__(256, 2)
void tgemm(const __nv_bfloat16* __restrict__ A, const __nv_bfloat16* __restrict__ B,
           float* __restrict__ C, int K3, int Nvalid, int Nstride) {
    extern __shared__ char dynsm[];
    const uint32_t sb = smem_u32(dynsm);
    const int tid = threadIdx.x;
    const int lane = tid & 31;
    const int wid = tid >> 5;
    const int wm = wid & 3;
    const int wn = wid >> 2;

    const int gridM = gridDim.x;
    const int gridN = gridDim.y;
    const int bid = blockIdx.y * gridM + blockIdx.x;
    const int GM = 16;
    const int group = bid / (GM * gridN);
    const int rem = bid - group * (GM * gridN);
    const int m0 = (group * GM + (rem % GM)) * 128;
    const int n0 = (rem / GM) * 128;
    const int nK = K3 >> 6;

    float acc[2][8][4];
#pragma unroll
    for (int i = 0; i < 2; i++)
#pragma unroll
        for (int j = 0; j < 8; j++)
#pragma unroll
            for (int q = 0; q < 4; q++) acc[i][j][q] = 0.f;

    gemm_load_stage(A, B, K3, m0, n0, tid, sb, 0, 0); CP_COMMIT();
    gemm_load_stage(A, B, K3, m0, n0, tid, sb, 1, 1); CP_COMMIT();

    const int a_row = wm * 32 + (lane & 15);
    const int a_chg = lane >> 4;
    const int b_g = lane >> 3;
    const int b_row = wn * 64 + ((b_g >> 1) << 3) + (lane & 7);
    const int b_chg = b_g & 1;

    int buf = 0, nbuf = 2;
    for (int i = 0; i < nK; i++) {
        asm volatile("cp.async.wait_group 1;" ::: "memory");
        __syncthreads();
        if (i + 2 < nK) gemm_load_stage(A, B, K3, m0, n0, tid, sb, nbuf, i + 2);
        CP_COMMIT();

        const uint32_t abase = sb + buf * GSTAGE_BYTES;
        const uint32_t bbase = abase + 16384;
#pragma unroll
        for (int kk = 0; kk < 4; kk++) {
            uint32_t af[2][4];
#pragma unroll
            for (int mi = 0; mi < 2; mi++) {
                const int row = a_row + mi * 16;
                const int ch = kk * 2 + a_chg;
                const int csw = ch ^ (row & 7);
                ldsm_x4(abase + row * 128 + csw * 16,
                        af[mi][0], af[mi][1], af[mi][2], af[mi][3]);
            }
            uint32_t bf[4][4];
#pragma unroll
            for (int nb = 0; nb < 4; nb++) {
                const int row = b_row + nb * 16;
                const int ch = kk * 2 + b_chg;
                const int csw = ch ^ (row & 7);
                ldsm_x4(bbase + row * 128 + csw * 16,
                        bf[nb][0], bf[nb][1], bf[nb][2], bf[nb][3]);
            }
#pragma unroll
            for (int mi = 0; mi < 2; mi++)
#pragma unroll
                for (int nb = 0; nb < 4; nb++) {
                    mma_bf16(acc[mi][nb * 2 + 0], af[mi], bf[nb][0], bf[nb][1]);
                    mma_bf16(acc[mi][nb * 2 + 1], af[mi], bf[nb][2], bf[nb][3]);
                }
        }
        buf = (buf + 1 == GSTAGES) ? 0 : buf + 1;
        nbuf = (nbuf + 1 == GSTAGES) ? 0 : nbuf + 1;
    }

    const int erow = (lane >> 2);
    const int ecol = (lane & 3) << 1;
#pragma unroll
    for (int mi = 0; mi < 2; mi++) {
        const int r = m0 + wm * 32 + mi * 16 + erow;
#pragma unroll
        for (int f = 0; f < 8; f++) {
            const int c = n0 + wn * 64 + (f >> 1) * 16 + (f & 1) * 8 + ecol;
            if (c < Nvalid) {
                *(float2*)(C + (size_t)r * Nstride + c) =
                    make_float2(acc[mi][f][0], acc[mi][f][1]);
                *(float2*)(C + (size_t)(r + 8) * Nstride + c) =
                    make_float2(acc[mi][f][2], acc[mi][f][3]);
            }
        }
    }
}

// ================= mega_mid: conv_silu + dtacum + pack_B2 in one grid =================
__global__ void mega_mid(const float* __restrict__ cw, const float* __restrict__ cb,
                         const float* __restrict__ dt_bias, const float* __restrict__ A_log,
                         const float* __restrict__ w_out) {
    __shared__ float s[CSZ];
    const int bx = blockIdx.x;
    const int by = blockIdx.y;
    const int tid = threadIdx.x;

    if (bx < 24) {
        const int c = bx * 256 + tid;
        const int tb = by * 8;
        const float w0 = cw[c * 4 + 0], w1 = cw[c * 4 + 1],
                    w2 = cw[c * 4 + 2], w3 = cw[c * 4 + 3];
        const float bias = cb[c];
        float v[11];
#pragma unroll
        for (int k = 0; k < 11; k++) {
            const int tt = tb - 3 + k;
            v[k] = (tt >= 0) ? g_proj[(size_t)tt * PROJD + INTERD + c] : 0.f;
        }
        if (c < INTERD) {
#pragma unroll
            for (int j = 0; j < 8; j++) {
                const float a = bias + v[j] * w0 + v[j + 1] * w1 + v[j + 2] * w2 + v[j + 3] * w3;
                g_hconv[(size_t)(tb + j) * CONVD + c] = a / (1.f + __expf(-a));
            }
        } else {
            const int cc = c - INTERD;
#pragma unroll
            for (int j = 0; j < 8; j++) {
                const float a = bias + v[j] * w0 + v[j + 1] * w1 + v[j + 2] * w2 + v[j + 3] * w3;
                const float y = a / (1.f + __expf(-a));
                const __nv_bfloat16 hb = __float2bfloat16(y);
                g_bch[(size_t)(tb + j) * BCW + cc] = hb;
                g_bcl[(size_t)(tb + j) * BCW + cc] =
                    __float2bfloat16(y - __bfloat162float(hb));
            }
        }
    } else if (bx < 26) {
        const int d = (bx - 24) * 512 + by;
        const int chunk = d >> 6;
        const int h = d & 63;
        const float Ah = -expf(A_log[h]);
        const float bias = dt_bias[h];
        const int t = chunk * CSZ + tid;
        const float x = g_proj[(size_t)t * PROJD + DTOFF + h] + bias;
        const float dt2 = (x > 20.f) ? x : log1pf(expf(x));
        g_dt2[t * NH + h] = dt2;
        s[tid] = Ah * dt2;
        for (int off = 1; off < CSZ; off <<= 1) {
            __syncthreads();
            const float v = (tid >= off) ? s[tid - off] : 0.f;
            __syncthreads();
            s[tid] += v;
        }
        g_acum[h * SS + t] = s[tid];
    } else {
        const int p = (bx - 26) * 512 + by;
        pack_core(w_out, g_B2, EMB, EMB, INTERD, 1, p, 2048);
    }
}

// ================= SSD via HMMA — register-resident Gw =================
// Stage2 A-fragments are built directly from the weighted Gram accumulators
// (accumulator and A-operand fragments tile identically). No Gw smem, no
// Gw syncs: 2 barriers per j-tile total.
#define S_CHI 0
#define S_CLO 65536
#define S_BHI 131072
#define S_BLO 147456
#define S_XHI 163840
#define S_XLO 172032
#define S_ACS 180224
#define SSD_DYN_SMEM (S_ACS + 1024)

__global__ __launch_bounds__(256, 1)
void ssd_hmma(const float* __restrict__ Dp) {
    extern __shared__ char sm[];
    const uint32_t sb = smem_u32(sm);
    float* acs = (float*)(sm + S_ACS);
    const int tid = threadIdx.x;
    const int lane = tid & 31;
    const int w = tid >> 5;
    const int chunk = blockIdx.x;
    const int h = blockIdx.y;
    const int t0 = chunk * CSZ;
    const int grp = h & 7;
    const int Bcol = grp * SN;
    const int Ccol = NG * SN + grp * SN;
    const int i0 = w * 32;

#pragma unroll 4
    for (int it = 0; it < 16; it++) {
        const int u = it * 256 + tid;
        const int i = u >> 4;
        const int nb = u & 15;
        const uint32_t dsw = i * 256 + ((nb ^ (i & 7)) << 4);
        const size_t gsrc = (size_t)(t0 + i) * BCW + Ccol + nb * 8;
        cp_async16(sb + S_CHI + dsw, g_bch + gsrc);
        cp_async16(sb + S_CLO + dsw, g_bcl + gsrc);
    }
    CP_COMMIT();

    acs[tid] = g_acum[h * SS + t0 + tid];

    float yacc[2][8][4];
#pragma unroll
    for (int mi = 0; mi < 2; mi++)
#pragma unroll
        for (int nb = 0; nb < 8; nb++)
#pragma unroll
            for (int q = 0; q < 4; q++) yacc[mi][nb][q] = 0.f;

    const int ro = lane >> 2;
    const int co = (lane & 3) * 2;

    for (int jt = 0; jt < 4; jt++) {
        const int jb = jt * 64;
        // B tile loads
#pragma unroll
        for (int it = 0; it < 4; it++) {
            const int u = it * 256 + tid;
            const int j = u >> 4;
            const int nb = u & 15;
            const uint32_t dsw = j * 256 + ((nb ^ (j & 7)) << 4);
            const size_t gsrc = (size_t)(t0 + jb + j) * BCW + Bcol + nb * 8;
            cp_async16(sb + S_BHI + dsw, g_bch + gsrc);
            cp_async16(sb + S_BLO + dsw, g_bcl + gsrc);
        }
        CP_COMMIT();
        // X convert (hid*dt2), TRANSPOSED [p][j]
#pragma unroll
        for (int it = 0; it < 4; it++) {
            const int u = it * 256 + tid;
            const int j = u >> 4;
            const int pb = (u & 15) * 4;
            const int tj = t0 + jb + j;
            float4 v = *(const float4*)(g_hconv + (size_t)tj * CONVD + h * HP + pb);
            const float sc = g_dt2[tj * NH + h];
            const float xv[4] = {v.x * sc, v.y * sc, v.z * sc, v.w * sc};
            const int wo = (j * 2) & 15;
            const int chn = j >> 3;
#pragma unroll
            for (int q = 0; q < 4; q++) {
                const int p = pb + q;
                const __nv_bfloat16 hb = __float2bfloat16(xv[q]);
                const __nv_bfloat16 lb = __float2bfloat16(xv[q] - __bfloat162float(hb));
                const uint32_t ad = p * 128 + ((chn ^ (p & 7)) << 4) + wo;
                *(__nv_bfloat16*)(sm + S_XHI + ad) = hb;
                *(__nv_bfloat16*)(sm + S_XLO + ad) = lb;
            }
        }
        asm volatile("cp.async.wait_group 0;" ::: "memory");
        __syncthreads();                      // sync1: B/C/X visible to all

        const float alast = acs[CSZ - 1];

        // ---- stage 1: Gram (own 32 i-rows x all 64 j), K = 128 x 3 terms ----
        float gacc[2][8][4];
#pragma unroll
        for (int mi = 0; mi < 2; mi++)
#pragma unroll
            for (int nb = 0; nb < 8; nb++)
#pragma unroll
                for (int q = 0; q < 4; q++) gacc[mi][nb][q] = 0.f;

        for (int term = 0; term < 3; term++) {
            const uint32_t Ab = sb + ((term == 1) ? S_CLO : S_CHI);
            const uint32_t Bb = sb + ((term == 2) ? S_BLO : S_BHI);
#pragma unroll
            for (int ks = 0; ks < 8; ks++) {
                uint32_t af[2][4];
#pragma unroll
                for (int mi = 0; mi < 2; mi++) {
                    const int row = i0 + mi * 16 + (lane & 15);
                    const int ch = 2 * ks + (lane >> 4);
                    const int csw = ch ^ (row & 7);
                    ldsm_x4(Ab + row * 256 + csw * 16,
                            af[mi][0], af[mi][1], af[mi][2], af[mi][3]);
                }
#pragma unroll
                for (int q = 0; q < 4; q++) {
                    const int bg = lane >> 3;
                    const int brow = q * 16 + ((bg >> 1) << 3) + (lane & 7);
                    const int bch = 2 * ks + (bg & 1);
                    const int bcsw = bch ^ (brow & 7);
                    uint32_t b0, b1, b2, b3;
                    ldsm_x4(Bb + brow * 256 + bcsw * 16, b0, b1, b2, b3);
                    mma_bf16(gacc[0][q * 2 + 0], af[0], b0, b1);
                    mma_bf16(gacc[0][q * 2 + 1], af[0], b2, b3);
                    mma_bf16(gacc[1][q * 2 + 0], af[1], b0, b1);
                    mma_bf16(gacc[1][q * 2 + 1], af[1], b2, b3);
                }
            }
        }

        // ---- weight in-place (SAFE two-exp form) + pack into A-fragments ----
        uint32_t ahi[2][4][4], alo[2][4][4];
#pragma unroll
        for (int mi = 0; mi < 2; mi++) {
            const int r1 = i0 + mi * 16 + ro;
            const int r2 = r1 + 8;
            const float a1 = acs[r1];
            const float a2 = acs[r2];
#pragma unroll
            for (int nb = 0; nb < 8; nb++) {
                const int cb = (nb >> 1) * 16 + (nb & 1) * 8 + co;
                const int jg = jb + cb;
                const float aj0 = acs[jg];
                const float aj1 = acs[jg + 1];
                float wv;
                wv = __expf(a1 - aj0 + alast) + ((jg     <= r1) ? __expf(a1 - aj0) : 0.f);
                gacc[mi][nb][0] *= wv;
                wv = __expf(a1 - aj1 + alast) + ((jg + 1 <= r1) ? __expf(a1 - aj1) : 0.f);
                gacc[mi][nb][1] *= wv;
                wv = __expf(a2 - aj0 + alast) + ((jg     <= r2) ? __expf(a2 - aj0) : 0.f);
                gacc[mi][nb][2] *= wv;
                wv = __expf(a2 - aj1 + alast) + ((jg + 1 <= r2) ? __expf(a2 - aj1) : 0.f);
                gacc[mi][nb][3] *= wv;
            }
            // pack: A-frag for k-tile t <- accumulators of n8 tiles 2t, 2t+1
#pragma unroll
            for (int t = 0; t < 4; t++) {
                const float g00 = gacc[mi][2 * t][0],     g01 = gacc[mi][2 * t][1];
                const float g02 = gacc[mi][2 * t][2],     g03 = gacc[mi][2 * t][3];
                const float g10 = gacc[mi][2 * t + 1][0], g11 = gacc[mi][2 * t + 1][1];
                const float g12 = gacc[mi][2 * t + 1][2], g13 = gacc[mi][2 * t + 1][3];
                ahi[mi][t][0] = pack_bf2(g00, g01);
                ahi[mi][t][1] = pack_bf2(g02, g03);
                ahi[mi][t][2] = pack_bf2(g10, g11);
                ahi[mi][t][3] = pack_bf2(g12, g13);
                alo[mi][t][0] = pack_bf2(bf16_res(g00), bf16_res(g01));
                alo[mi][t][1] = pack_bf2(bf16_res(g02), bf16_res(g03));
                alo[mi][t][2] = pack_bf2(bf16_res(g10), bf16_res(g11));
                alo[mi][t][3] = pack_bf2(bf16_res(g12), bf16_res(g13));
            }
        }

        // ---- stage 2: Y += Gw @ X^T (A from registers, B = X from smem) ----
        for (int term = 0; term < 3; term++) {
            const uint32_t Bb = sb + ((term == 2) ? S_XLO : S_XHI);
            const bool useLo = (term == 1);
#pragma unroll
            for (int ks = 0; ks < 4; ks++) {
                const uint32_t* a0 = useLo ? alo[0][ks] : ahi[0][ks];
                const uint32_t* a1 = useLo ? alo[1][ks] : ahi[1][ks];
#pragma unroll
                for (int q = 0; q < 4; q++) {
                    const int bg = lane >> 3;
                    const int brow = q * 16 + ((bg >> 1) << 3) + (lane & 7);
                    const int bch = 2 * ks + (bg & 1);
                    const int bcsw = bch ^ (brow & 7);
                    uint32_t b0, b1, b2, b3;
                    ldsm_x4(Bb + brow * 128 + bcsw * 16, b0, b1, b2, b3);
                    mma_bf16(yacc[0][q * 2 + 0], a0, b0, b1);
                    mma_bf16(yacc[0][q * 2 + 1], a0, b2, b3);
                    mma_bf16(yacc[1][q * 2 + 0], a1, b0, b1);
                    mma_bf16(yacc[1][q * 2 + 1], a1, b2, b3);
                }
            }
        }
        __syncthreads();                      // sync2: end of jt (protect B/X)
    }

    const float Dh = Dp[h];
#pragma unroll
    for (int mi = 0; mi < 2; mi++) {
        const int r1 = t0 + i0 + mi * 16 + ro;
        const int r2 = r1 + 8;
#pragma unroll
        for (int nb = 0; nb < 8; nb++) {
            const int p = (nb >> 1) * 16 + (nb & 1) * 8 + co;
            const float2 h1 = *(const float2*)(g_hconv + (size_t)r1 * CONVD + h * HP + p);
            const float2 h2 = *(const float2*)(g_hconv + (size_t)r2 * CONVD + h * HP + p);
            *(float2*)(g_y + (size_t)r1 * INTERD + h * HP + p) =
                make_float2(yacc[mi][nb][0] + Dh * h1.x, yacc[mi][nb][1] + Dh * h1.y);
            *(float2*)(g_y + (size_t)r2 * INTERD + h * HP + p) =
                make_float2(yacc[mi][nb][2] + Dh * h2.x, yacc[mi][nb][3] + Dh * h2.y);
        }
    }
}

// ---------------- gate silu + RMSNorm + split-bf16 A-pack (fused) ----------------
__global__ void norm_pack_kernel(const float* __restrict__ norm_w) {
    const int t = blockIdx.x;
    const int tid = threadIdx.x;
    __shared__ float red[256];
    __shared__ float yg_s[INTERD];
    float local = 0.f;
    for (int c = tid * 4; c < INTERD; c += 1024) {
        const float4 g4 = *(const float4*)(g_proj + (size_t)t * PROJD + c);
        const float4 y4 = *(const float4*)(g_y + (size_t)t * INTERD + c);
        const float yg0 = y4.x * (g4.x / (1.f + __expf(-g4.x)));
        const float yg1 = y4.y * (g4.y / (1.f + __expf(-g4.y)));
        const float yg2 = y4.z * (g4.z / (1.f + __expf(-g4.z)));
        const float yg3 = y4.w * (g4.w / (1.f + __expf(-g4.w)));
        *(float4*)(yg_s + c) = make_float4(yg0, yg1, yg2, yg3);
        local += yg0 * yg0 + yg1 * yg1 + yg2 * yg2 + yg3 * yg3;
    }
    red[tid] = local;
    __syncthreads();
    for (int s = 128; s > 0; s >>= 1) {
        if (tid < s) red[tid] += red[tid + s];
        __syncthreads();
    }
    const float rstd = rsqrtf(red[0] / (float)INTERD + 1e-6f);
    __nv_bfloat16* dst = g_Apack + (size_t)t * 3 * INTERD;
    for (int c = tid * 4; c < INTERD; c += 1024) {
        union { __nv_bfloat16 h[4]; uint2 u; } uh, ul;
#pragma unroll
        for (int i = 0; i < 4; i++) {
            const float v = norm_w[c + i] * yg_s[c + i] * rstd;
            uh.h[i] = __float2bfloat16(v);
            ul.h[i] = __float2bfloat16(v - __bfloat162float(uh.h[i]));
        }
        *(uint2*)(dst + c) = uh.u;
        *(uint2*)(dst + INTERD + c) = ul.u;
        *(uint2*)(dst + 2 * INTERD + c) = uh.u;
    }
}

// ---------------- launch ----------------
extern "C" void kernel_launch(void* const* d_in, const int* in_sizes, int n_in,
                              void* d_out, int out_size) {
    (void)in_sizes; (void)n_in; (void)out_size;
    const float* x       = (const float*)d_in[0];
    const float* w_in    = (const float*)d_in[1];
    const float* conv_w  = (const float*)d_in[2];
    const float* conv_b  = (const float*)d_in[3];
    const float* dt_bias = (const float*)d_in[4];
    const float* A_log   = (const float*)d_in[5];
    const float* Dv      = (const float*)d_in[6];
    const float* norm_w  = (const float*)d_in[7];
    const float* w_out   = (const float*)d_in[8];
    float* out = (float*)d_out;

    float* p_proj = nullptr;
    __nv_bfloat16* p_Apack = nullptr;
    __nv_bfloat16* p_B1 = nullptr;
    __nv_bfloat16* p_B2 = nullptr;
    cudaGetSymbolAddress((void**)&p_proj, g_proj);
    cudaGetSymbolAddress((void**)&p_Apack, g_Apack);
    cudaGetSymbolAddress((void**)&p_B1, g_B1);
    cudaGetSymbolAddress((void**)&p_B2, g_B2);

    cudaFuncSetAttribute(tgemm, cudaFuncAttributeMaxDynamicSharedMemorySize, GEMM_DYN_SMEM);
    cudaFuncSetAttribute(ssd_hmma, cudaFuncAttributeMaxDynamicSharedMemorySize, SSD_DYN_SMEM);

    // 1) combined packs for GEMM1 (A + B1)
    mega_pre<<<6144, 256>>>(x, w_in);
    // 2) GEMM1: proj = X @ W_in^T
    tgemm<<<dim3(SS / 128, PROJPAD / 128), 256, GEMM_DYN_SMEM>>>(
        p_Apack, p_B1, p_proj, 3 * EMB, PROJD, PROJD);
    // 3) combined conv + dtacum + pack_B2
    mega_mid<<<dim3(30, 512), 256>>>(conv_w, conv_b, dt_bias, A_log, w_out);
    // 4) SSD
    ssd_hmma<<<dim3(NCH, NH), 256, SSD_DYN_SMEM>>>(Dv);
    // 5) gate + norm + A-pack
    norm_pack_kernel<<<SS, 256>>>(norm_w);
    // 6) GEMM2: out = normed @ W_out^T
    tgemm<<<dim3(SS / 128, EMB / 128), 256, GEMM_DYN_SMEM>>>(
        p_Apack, p_B2, out, 3 * INTERD, EMB, EMB);
}